// round 10
// baseline (speedup 1.0000x reference)
#include <cuda_runtime.h>
#include <cuda_fp16.h>
#include <cstdint>

// Problem shape (fixed by setup_inputs)
#define BQ 8
#define SQ 4096
#define DD 1024
#define DH 512
#define MM (BQ * SQ)           // 32768 tokens

#define THRESHOLD 0.1f
#define EPSV 1e-05f
#define ZTHR (-0.10986122886681098f)   // atanh(2*0.1-1)/10
#define BAND 3e-3f
#define MAXFLAG 8192

// GEMM tiling
#define TM 128                 // tokens per CTA
#define TN 128                 // hidden units per CTA
#define BK 64                  // K per chunk
#define NCH (DD / BK)          // 16
#define NG (DH / TN)           // 4 N-groups

// smem layout (bytes). A: 128 rows x 128B (64 fp16, x-hi only).
// B: 2 planes (w-hi, w-lo) of 128 rows x 128B. Double buffered.
#define SM_B1   0              // 128 floats
#define SM_W2   512
#define SM_RED  1024           // float[128][2]
#define SM_A    2048           // [stage] 2 x 16384
#define SM_B    (SM_A + 2*16384)          // [stage][plane] 2 x 2 x 16384
#define SM_TOT  (SM_B + 2*32768)          // 100352

// Device scratch
__device__ __half g_w1t[2][DH * DD];   // [split][n*DD + k] transposed W1
__device__ float g_yp[NG][MM];         // per-N-group partial logits
__device__ float g_z[MM];              // full logits (incl b2)
__device__ float g_yfin[MM];           // final gate values
__device__ int   g_len[BQ];            // valid lengths per batch
__device__ int   g_idx[BQ][SQ];
__device__ int   g_newlen[BQ];
__device__ int   g_nflag;
__device__ int   g_flag[MAXFLAG];

// ---------------------------------------------------------------------------
__device__ __forceinline__ uint32_t smem_u32(const void* p) {
    uint32_t a;
    asm("{ .reg .u64 t; cvta.to.shared.u64 t, %1; cvt.u32.u64 %0, t; }"
        : "=r"(a) : "l"(p));
    return a;
}
__device__ __forceinline__ void ldm_x4(uint32_t& r0, uint32_t& r1,
                                       uint32_t& r2, uint32_t& r3, uint32_t addr) {
    asm volatile("ldmatrix.sync.aligned.m8n8.x4.shared.b16 {%0,%1,%2,%3}, [%4];"
                 : "=r"(r0), "=r"(r1), "=r"(r2), "=r"(r3) : "r"(addr));
}
__device__ __forceinline__ void mma_f16(float* d, const uint32_t* a,
                                        uint32_t b0, uint32_t b1) {
    asm volatile(
        "mma.sync.aligned.m16n8k16.row.col.f32.f16.f16.f32 "
        "{%0,%1,%2,%3}, {%4,%5,%6,%7}, {%8,%9}, {%0,%1,%2,%3};"
        : "+f"(d[0]), "+f"(d[1]), "+f"(d[2]), "+f"(d[3])
        : "r"(a[0]), "r"(a[1]), "r"(a[2]), "r"(a[3]), "r"(b0), "r"(b1));
}
__device__ __forceinline__ uint32_t packh2(float a, float b) {
    __half2 h = __floats2half2_rn(a, b);
    return *(uint32_t*)&h;
}

// ---------------------------------------------------------------------------
// Kernel P: per-batch valid length from pad (4-byte elems, nonzero = padded).
// ---------------------------------------------------------------------------
__global__ __launch_bounds__(256, 4)
void pad_len_kernel(const unsigned int* __restrict__ pad)
{
    __shared__ int ired[256];
    const int b = blockIdx.x;
    const int tid = threadIdx.x;
    if (b == 0 && tid == 0) g_nflag = 0;
    int lc = 0;
    for (int s = tid; s < SQ; s += 256)
        lc += (pad[b * SQ + s] == 0u) ? 1 : 0;
    ired[tid] = lc;
    __syncthreads();
    for (int o = 128; o > 0; o >>= 1) {
        if (tid < o) ired[tid] += ired[tid + o];
        __syncthreads();
    }
    if (tid == 0) g_len[b] = ired[0];
}

// ---------------------------------------------------------------------------
// Kernel 0: coalesced tiled transpose + 2-way fp16 split of W1.
// ---------------------------------------------------------------------------
__global__ __launch_bounds__(256, 6)
void w1_split_kernel(const float* __restrict__ W1) {
    __shared__ float tile[32][33];
    const int k0 = blockIdx.x * 32;
    const int n0 = blockIdx.y * 32;
    const int tx = threadIdx.x;   // 0..31
    const int ty = threadIdx.y;   // 0..7

#pragma unroll
    for (int j = 0; j < 4; j++) {
        const int k = k0 + ty + j * 8;
        tile[ty + j * 8][tx] = W1[(size_t)k * DH + n0 + tx];
    }
    __syncthreads();

#pragma unroll
    for (int j = 0; j < 4; j++) {
        const int n = n0 + ty + j * 8;
        const float a = tile[tx][ty + j * 8];
        __half h = __float2half_rn(a);
        __half l = __float2half_rn(a - __half2float(h));
        g_w1t[0][(size_t)n * DD + k0 + tx] = h;
        g_w1t[1][(size_t)n * DD + k0 + tx] = l;
    }
}

// ---------------------------------------------------------------------------
// Kernel A: HMMA fp16 2-product (xh*wh + xh*wl) GEMM + fused gate epilogue.
// BK=64, double buffered, 2 CTAs/SM. Padded M-tiles skipped.
// ---------------------------------------------------------------------------
__global__ __launch_bounds__(256, 2)
void gemm_hmma(const float* __restrict__ X,
               const float* __restrict__ b1,
               const float* __restrict__ W2)
{
    extern __shared__ char smem[];
    const uint32_t sbase = smem_u32(smem);
    const int tid = threadIdx.x;
    const int wid = tid >> 5;
    const int lane = tid & 31;
    const int wm = wid & 3;          // M quadrant (32 rows)
    const int wn = wid >> 2;         // N half (64 cols)
    const int n0 = blockIdx.x * TN;
    const int m0 = blockIdx.y * TM;

    // Early exit: tile fully in trailing padding -> logits never read.
    const int bq = m0 >> 12;
    const int s0 = m0 & (SQ - 1);
    if (s0 >= g_len[bq]) return;

    float* b1s = (float*)(smem + SM_B1);
    float* w2s = (float*)(smem + SM_W2);
    float (*red)[2] = (float(*)[2])(smem + SM_RED);
    if (tid < TN) {
        b1s[tid] = b1[n0 + tid];
        w2s[tid] = W2[n0 + tid];
    }

    float acc[2][8][4];
#pragma unroll
    for (int mt = 0; mt < 2; mt++)
#pragma unroll
        for (int nt = 0; nt < 8; nt++)
#pragma unroll
            for (int e = 0; e < 4; e++) acc[mt][nt][e] = 0.0f;

    // Staging registers
    float4 av[8];             // A: 32 floats (half of 64-K row)
    uint4  bv[2][4];          // B: [split][4 x 16B] (32 fp16 each)

    const int lrow = tid >> 1;           // 0..127
    const int half = tid & 1;            // which 32-K half of the row
    const int rx = lrow & 7;
    const uint32_t rb = (uint32_t)lrow * 128u;

    const float* Xp = X + (size_t)(m0 + lrow) * DD + half * 32;
    const __half* Bp[2];
#pragma unroll
    for (int sp = 0; sp < 2; sp++)
        Bp[sp] = g_w1t[sp] + (size_t)(n0 + lrow) * DD + half * 32;

#define LDG_CHUNK(c) do {                                                   \
    const int _k0 = (c) * BK;                                               \
    _Pragma("unroll")                                                       \
    for (int j = 0; j < 8; j++)                                             \
        av[j] = *(const float4*)(Xp + _k0 + j * 4);                         \
    _Pragma("unroll")                                                       \
    for (int sp = 0; sp < 2; sp++)                                          \
        _Pragma("unroll")                                                   \
        for (int j = 0; j < 4; j++)                                         \
            bv[sp][j] = *(const uint4*)(Bp[sp] + _k0 + j * 8);              \
} while (0)

#define STS_CHUNK(st) do {                                                  \
    _Pragma("unroll")                                                       \
    for (int jj = 0; jj < 4; jj++) {                                        \
        const float* f = (const float*)&av[jj * 2];                         \
        uint4 hx;                                                           \
        hx.x = packh2(f[0], f[1]);                                          \
        hx.y = packh2(f[2], f[3]);                                          \
        hx.z = packh2(f[4], f[5]);                                          \
        hx.w = packh2(f[6], f[7]);                                          \
        const int chh = half * 4 + jj;                                      \
        const uint32_t co = (uint32_t)((chh ^ rx) * 16);                    \
        *(uint4*)(smem + SM_A + (st) * 16384 + rb + co) = hx;               \
        *(uint4*)(smem + SM_B + (st) * 32768 + rb + co) = bv[0][jj];        \
        *(uint4*)(smem + SM_B + (st) * 32768 + 16384 + rb + co) = bv[1][jj];\
    }                                                                       \
} while (0)

    // Prologue
    LDG_CHUNK(0);
    STS_CHUNK(0);
    LDG_CHUNK(1);
    __syncthreads();

    for (int c = 0; c < NCH; c++) {
        const int st = c & 1;
        if (c + 1 < NCH) STS_CHUNK((c + 1) & 1);
        if (c + 2 < NCH) LDG_CHUNK(c + 2);

        // Compute from buf st
#pragma unroll
        for (int ks = 0; ks < 4; ks++) {
            uint32_t a[2][4];        // [mtile][4]
            uint32_t bb[2][4][4];    // [split][npair][4]
            const int cc = ks * 2 + (lane >> 4);
#pragma unroll
            for (int mt = 0; mt < 2; mt++) {
                const int r = wm * 32 + mt * 16 + (lane & 15);
                const uint32_t addr = sbase + SM_A + st * 16384
                                    + r * 128 + ((cc ^ (r & 7)) * 16);
                ldm_x4(a[mt][0], a[mt][1], a[mt][2], a[mt][3], addr);
            }
#pragma unroll
            for (int sp = 0; sp < 2; sp++)
#pragma unroll
                for (int np = 0; np < 4; np++) {
                    const int r = wn * 64 + np * 16 + (lane & 15);
                    const uint32_t addr = sbase + SM_B + st * 32768 + sp * 16384
                                        + r * 128 + ((cc ^ (r & 7)) * 16);
                    ldm_x4(bb[sp][np][0], bb[sp][np][1], bb[sp][np][2], bb[sp][np][3], addr);
                }
#pragma unroll
            for (int mt = 0; mt < 2; mt++)
#pragma unroll
                for (int nt = 0; nt < 8; nt++) {
                    const int np = nt >> 1, sel = nt & 1;
                    mma_f16(acc[mt][nt], a[mt], bb[0][np][sel], bb[0][np][sel + 2]);
                    mma_f16(acc[mt][nt], a[mt], bb[1][np][sel], bb[1][np][sel + 2]);
                }
        }
        __syncthreads();
    }

    // Epilogue: p = sum_cols relu(acc + b1) * w2, reduce across quads + wn.
#pragma unroll
    for (int mt = 0; mt < 2; mt++) {
        float p0 = 0.0f, p1 = 0.0f;
#pragma unroll
        for (int nt = 0; nt < 8; nt++) {
            const int cl = wn * 64 + nt * 8 + (lane & 3) * 2;
            const float w0 = w2s[cl], w1v = w2s[cl + 1];
            const float c0 = b1s[cl], c1 = b1s[cl + 1];
            p0 = fmaf(fmaxf(acc[mt][nt][0] + c0, 0.0f), w0, p0);
            p0 = fmaf(fmaxf(acc[mt][nt][1] + c1, 0.0f), w1v, p0);
            p1 = fmaf(fmaxf(acc[mt][nt][2] + c0, 0.0f), w0, p1);
            p1 = fmaf(fmaxf(acc[mt][nt][3] + c1, 0.0f), w1v, p1);
        }
        p0 += __shfl_xor_sync(0xffffffffu, p0, 1);
        p0 += __shfl_xor_sync(0xffffffffu, p0, 2);
        p1 += __shfl_xor_sync(0xffffffffu, p1, 1);
        p1 += __shfl_xor_sync(0xffffffffu, p1, 2);
        if ((lane & 3) == 0) {
            const int r0 = wm * 32 + mt * 16 + (lane >> 2);
            red[r0][wn] = p0;
            red[r0 + 8][wn] = p1;
        }
    }
    __syncthreads();
    if (tid < TM)
        g_yp[blockIdx.x][m0 + tid] = red[tid][0] + red[tid][1];
}

// ---------------------------------------------------------------------------
// Kernel B1: sum partials -> z, flag tokens within BAND of threshold.
// ---------------------------------------------------------------------------
__global__ __launch_bounds__(256, 8)
void zflag_kernel(const float* __restrict__ b2)
{
    const int t = blockIdx.x * 256 + threadIdx.x;
    const int b = t >> 12;
    const int s = t & (SQ - 1);
    if (s >= g_len[b]) { g_z[t] = 0.0f; return; }
    float z = g_yp[0][t] + g_yp[1][t] + g_yp[2][t] + g_yp[3][t] + b2[0];
    g_z[t] = z;
    if (fabsf(z - ZTHR) < BAND) {
        int i = atomicAdd(&g_nflag, 1);
        if (i < MAXFLAG) g_flag[i] = t;
    }
}

// ---------------------------------------------------------------------------
// Kernel R: exact fp32 recompute of flagged tokens' logits.
// One block (1024 thr) per flagged token: 8 k-groups x 128 h-quads.
// ---------------------------------------------------------------------------
__global__ __launch_bounds__(1024, 1)
void refine_kernel(const float* __restrict__ X,
                   const float* __restrict__ W1,
                   const float* __restrict__ b1,
                   const float* __restrict__ W2,
                   const float* __restrict__ b2)
{
    __shared__ float  xs[DD];           // 4KB
    __shared__ float4 part[8][128];     // 16KB
    __shared__ float  rr[4];
    const int tid = threadIdx.x;
    const int kg = tid >> 7;            // 0..7
    const int hq = tid & 127;           // h quad: h = hq*4..hq*4+3
    int n = g_nflag;
    if (n > MAXFLAG) n = MAXFLAG;

    for (int i = blockIdx.x; i < n; i += gridDim.x) {
        const int t = g_flag[i];
        if (tid < DD) xs[tid] = X[(size_t)t * DD + tid];
        __syncthreads();

        const float4* Wp = (const float4*)W1 + hq;
        float4 acc = make_float4(0.0f, 0.0f, 0.0f, 0.0f);
        const int k0 = kg * 128;
#pragma unroll 8
        for (int k = k0; k < k0 + 128; k++) {
            const float xk = xs[k];
            const float4 w = Wp[(size_t)k * (DH / 4)];
            acc.x = fmaf(xk, w.x, acc.x);
            acc.y = fmaf(xk, w.y, acc.y);
            acc.z = fmaf(xk, w.z, acc.z);
            acc.w = fmaf(xk, w.w, acc.w);
        }
        part[kg][hq] = acc;
        __syncthreads();

        if (tid < 128) {
            float4 s = part[0][tid];
#pragma unroll
            for (int g = 1; g < 8; g++) {
                const float4 q = part[g][tid];
                s.x += q.x; s.y += q.y; s.z += q.z; s.w += q.w;
            }
            const float4 bb = ((const float4*)b1)[tid];
            const float4 ww = ((const float4*)W2)[tid];
            float p;
            p  = fmaxf(s.x + bb.x, 0.0f) * ww.x;
            p += fmaxf(s.y + bb.y, 0.0f) * ww.y;
            p += fmaxf(s.z + bb.z, 0.0f) * ww.z;
            p += fmaxf(s.w + bb.w, 0.0f) * ww.w;
            p += __shfl_xor_sync(0xffffffffu, p, 16);
            p += __shfl_xor_sync(0xffffffffu, p, 8);
            p += __shfl_xor_sync(0xffffffffu, p, 4);
            p += __shfl_xor_sync(0xffffffffu, p, 2);
            p += __shfl_xor_sync(0xffffffffu, p, 1);
            if ((tid & 31) == 0) rr[tid >> 5] = p;
        }
        __syncthreads();
        if (tid == 0) g_z[t] = rr[0] + rr[1] + rr[2] + rr[3] + b2[0];
        __syncthreads();
    }
}

// ---------------------------------------------------------------------------
// Kernel B2: per-batch squash, max/adjust, compaction. Uses g_len.
// ---------------------------------------------------------------------------
__global__ __launch_bounds__(256, 1)
void gate_select_kernel(float* __restrict__ vpad_out, int write_vpad)
{
    const int b = blockIdx.x;
    const int tid = threadIdx.x;

    __shared__ float ysm[SQ];
    __shared__ float fred[256];
    __shared__ int   cnt[256];

    const int length = g_len[b];

    float mx = 0.0f;
    for (int s = tid; s < SQ; s += 256) {
        float y = (s < length)
                ? (1.0f + tanhf(10.0f * g_z[b * SQ + s])) * 0.5f : 0.0f;
        ysm[s] = y;
        mx = fmaxf(mx, y);
    }
    fred[tid] = mx;
    __syncthreads();
    for (int o = 128; o > 0; o >>= 1) {
        if (tid < o) fred[tid] = fmaxf(fred[tid], fred[tid + o]);
        __syncthreads();
    }
    const float adjust = fmaxf(0.0f, EPSV + THRESHOLD - fred[0]);
    __syncthreads();

    for (int s = tid; s < SQ; s += 256) {
        float yf = ysm[s] + adjust;
        ysm[s] = yf;
        g_yfin[b * SQ + s] = yf;
    }
    __syncthreads();

    const int CH = SQ / 256;
    const int base = tid * CH;
    int c = 0;
#pragma unroll
    for (int i = 0; i < CH; i++) {
        int s = base + i;
        c += (ysm[s] > THRESHOLD && s < length) ? 1 : 0;
    }
    cnt[tid] = c;
    __syncthreads();
    for (int o = 1; o < 256; o <<= 1) {
        int v = (tid >= o) ? cnt[tid - o] : 0;
        __syncthreads();
        cnt[tid] += v;
        __syncthreads();
    }
    int off = cnt[tid] - c;
#pragma unroll
    for (int i = 0; i < CH; i++) {
        int s = base + i;
        if (ysm[s] > THRESHOLD && s < length) g_idx[b][off++] = s;
    }
    const int nl = cnt[255];
    if (tid == 0) g_newlen[b] = nl;

    if (write_vpad) {
        for (int s = tid; s < SQ; s += 256)
            vpad_out[b * SQ + s] = (s >= nl) ? 1.0f : 0.0f;
    }
}

// ---------------------------------------------------------------------------
// Kernel C: scatter compacted rows.
// ---------------------------------------------------------------------------
__global__ __launch_bounds__(256, 4)
void scatter_kernel(const float* __restrict__ X, float* __restrict__ V)
{
    const int b = blockIdx.y;
    const int r = blockIdx.x;
    const int tid = threadIdx.x;
    const int nl = g_newlen[b];

    float4* vrow = (float4*)(V + ((size_t)b * SQ + r) * DD);
    if (r < nl) {
        const int s = g_idx[b][r];
        const float g = g_yfin[b * SQ + s];
        const float4* xrow = (const float4*)(X + ((size_t)b * SQ + s) * DD);
        float4 xv = xrow[tid];
        vrow[tid] = make_float4(xv.x * g, xv.y * g, xv.z * g, xv.w * g);
    } else {
        vrow[tid] = make_float4(0.0f, 0.0f, 0.0f, 0.0f);
    }
}

// ---------------------------------------------------------------------------
extern "C" void kernel_launch(void* const* d_in, const int* in_sizes, int n_in,
                              void* d_out, int out_size)
{
    const float*        x   = (const float*)d_in[0];
    const unsigned int* pad = (const unsigned int*)d_in[1];
    const float*        W1  = (const float*)d_in[2];
    const float*        b1  = (const float*)d_in[3];
    const float*        W2  = (const float*)d_in[4];
    const float*        b2  = (const float*)d_in[5];
    float* out = (float*)d_out;

    const long v_elems = (long)MM * DD;
    int write_vpad = (out_size > v_elems) ? 1 : 0;
    float* vpad = out + v_elems;

    cudaFuncSetAttribute(gemm_hmma,
                         cudaFuncAttributeMaxDynamicSharedMemorySize, SM_TOT);

    pad_len_kernel<<<BQ, 256>>>(pad);
    w1_split_kernel<<<dim3(DD / 32, DH / 32), dim3(32, 8)>>>(W1);
    gemm_hmma<<<dim3(NG, MM / TM), 256, SM_TOT>>>(x, b1, W2);
    zflag_kernel<<<MM / 256, 256>>>(b2);
    refine_kernel<<<64, 1024>>>(x, W1, b1, W2, b2);
    gate_select_kernel<<<BQ, 256>>>(vpad, write_vpad);
    scatter_kernel<<<dim3(SQ, BQ), 256>>>(x, out);
}

// round 11
// speedup vs baseline: 1.4932x; 1.4932x over previous
#include <cuda_runtime.h>
#include <cuda_fp16.h>
#include <cstdint>

// Problem shape (fixed by setup_inputs)
#define BQ 8
#define SQ 4096
#define DD 1024
#define DH 512
#define MM (BQ * SQ)           // 32768 tokens

#define THRESHOLD 0.1f
#define EPSV 1e-05f
#define ZTHR (-0.10986122886681098f)   // atanh(2*0.1-1)/10
#define BAND 3e-3f
#define MAXFLAG 8192

// GEMM tiling
#define TM 128                 // tokens per CTA
#define TN 128                 // hidden units per CTA
#define BK 64                  // K per chunk
#define NCH (DD / BK)          // 16
#define NG (DH / TN)           // 4 N-groups

// smem: per stage = A(16KB) + B hi/lo (2x16KB) = 48KB; 2 stages = 96KB.
#define SM_B1    0             // 128 floats
#define SM_W2    512
#define SM_RED   1024          // float[128][2]
#define SM_TILE  2048
#define STAGE_SZ 49152
#define SM_TOT   (SM_TILE + 2 * STAGE_SZ)   // 100352

// Device scratch
__device__ __half g_xh[MM * DD];       // X rounded to fp16 (64MB)
__device__ __half g_w1t[2][DH * DD];   // [split][n*DD + k] transposed W1
__device__ float g_yp[NG][MM];         // per-N-group partial logits
__device__ float g_z[MM];              // full logits (incl b2)
__device__ float g_yfin[MM];           // final gate values
__device__ int   g_len[BQ];            // valid lengths per batch
__device__ int   g_idx[BQ][SQ];
__device__ int   g_newlen[BQ];
__device__ int   g_nflag;
__device__ int   g_flag[MAXFLAG];

// ---------------------------------------------------------------------------
__device__ __forceinline__ uint32_t smem_u32(const void* p) {
    uint32_t a;
    asm("{ .reg .u64 t; cvta.to.shared.u64 t, %1; cvt.u32.u64 %0, t; }"
        : "=r"(a) : "l"(p));
    return a;
}
__device__ __forceinline__ void ldm_x4(uint32_t& r0, uint32_t& r1,
                                       uint32_t& r2, uint32_t& r3, uint32_t addr) {
    asm volatile("ldmatrix.sync.aligned.m8n8.x4.shared.b16 {%0,%1,%2,%3}, [%4];"
                 : "=r"(r0), "=r"(r1), "=r"(r2), "=r"(r3) : "r"(addr));
}
__device__ __forceinline__ void mma_f16(float* d, const uint32_t* a,
                                        uint32_t b0, uint32_t b1) {
    asm volatile(
        "mma.sync.aligned.m16n8k16.row.col.f32.f16.f16.f32 "
        "{%0,%1,%2,%3}, {%4,%5,%6,%7}, {%8,%9}, {%0,%1,%2,%3};"
        : "+f"(d[0]), "+f"(d[1]), "+f"(d[2]), "+f"(d[3])
        : "r"(a[0]), "r"(a[1]), "r"(a[2]), "r"(a[3]), "r"(b0), "r"(b1));
}
__device__ __forceinline__ void cp16(uint32_t dst, const void* src) {
    asm volatile("cp.async.cg.shared.global [%0], [%1], 16;"
                 :: "r"(dst), "l"(src));
}
#define CP_COMMIT() asm volatile("cp.async.commit_group;" ::: "memory")
#define CP_WAIT1()  asm volatile("cp.async.wait_group 1;" ::: "memory")

// ---------------------------------------------------------------------------
// Kernel P: per-batch valid length from pad (4-byte elems, nonzero = padded).
// ---------------------------------------------------------------------------
__global__ __launch_bounds__(256, 4)
void pad_len_kernel(const unsigned int* __restrict__ pad)
{
    __shared__ int ired[256];
    const int b = blockIdx.x;
    const int tid = threadIdx.x;
    if (b == 0 && tid == 0) g_nflag = 0;
    int lc = 0;
    for (int s = tid; s < SQ; s += 256)
        lc += (pad[b * SQ + s] == 0u) ? 1 : 0;
    ired[tid] = lc;
    __syncthreads();
    for (int o = 128; o > 0; o >>= 1) {
        if (tid < o) ired[tid] += ired[tid + o];
        __syncthreads();
    }
    if (tid == 0) g_len[b] = ired[0];
}

// ---------------------------------------------------------------------------
// Kernel X: convert X fp32 -> fp16 (round-to-nearest).
// ---------------------------------------------------------------------------
__global__ __launch_bounds__(256, 8)
void xconv_kernel(const float* __restrict__ X)
{
    const int i = blockIdx.x * 256 + threadIdx.x;     // per 4 elements
    const float4 v = ((const float4*)X)[i];
    __half2 h0 = __floats2half2_rn(v.x, v.y);
    __half2 h1 = __floats2half2_rn(v.z, v.w);
    uint2 o;
    o.x = *(uint32_t*)&h0;
    o.y = *(uint32_t*)&h1;
    ((uint2*)g_xh)[i] = o;
}

// ---------------------------------------------------------------------------
// Kernel 0: coalesced tiled transpose + 2-way fp16 split of W1.
// ---------------------------------------------------------------------------
__global__ __launch_bounds__(256, 6)
void w1_split_kernel(const float* __restrict__ W1) {
    __shared__ float tile[32][33];
    const int k0 = blockIdx.x * 32;
    const int n0 = blockIdx.y * 32;
    const int tx = threadIdx.x;   // 0..31
    const int ty = threadIdx.y;   // 0..7

#pragma unroll
    for (int j = 0; j < 4; j++) {
        const int k = k0 + ty + j * 8;
        tile[ty + j * 8][tx] = W1[(size_t)k * DH + n0 + tx];
    }
    __syncthreads();

#pragma unroll
    for (int j = 0; j < 4; j++) {
        const int n = n0 + ty + j * 8;
        const float a = tile[tx][ty + j * 8];
        __half h = __float2half_rn(a);
        __half l = __float2half_rn(a - __half2float(h));
        g_w1t[0][(size_t)n * DD + k0 + tx] = h;
        g_w1t[1][(size_t)n * DD + k0 + tx] = l;
    }
}

// ---------------------------------------------------------------------------
// Kernel A: HMMA fp16 2-product (xh*wh + xh*wl) GEMM, cp.async pipeline.
// All operands fp16 in gmem -> LDGSTS straight to swizzled smem, no staging
// regs, no STS. 2 stages, 2 CTAs/SM. Padded M-tiles skipped.
// ---------------------------------------------------------------------------
__global__ __launch_bounds__(256, 2)
void gemm_hmma(const float* __restrict__ b1,
               const float* __restrict__ W2)
{
    extern __shared__ char smem[];
    const uint32_t sbase = smem_u32(smem);
    const int tid = threadIdx.x;
    const int wid = tid >> 5;
    const int lane = tid & 31;
    const int wm = wid & 3;          // M quadrant (32 rows)
    const int wn = wid >> 2;         // N half (64 cols)
    const int n0 = blockIdx.x * TN;
    const int m0 = blockIdx.y * TM;

    // Early exit: tile fully in trailing padding -> logits never read.
    const int bq = m0 >> 12;
    const int s0 = m0 & (SQ - 1);
    if (s0 >= g_len[bq]) return;

    float* b1s = (float*)(smem + SM_B1);
    float* w2s = (float*)(smem + SM_W2);
    float (*red)[2] = (float(*)[2])(smem + SM_RED);
    if (tid < TN) {
        b1s[tid] = b1[n0 + tid];
        w2s[tid] = W2[n0 + tid];
    }

    float acc[2][8][4];
#pragma unroll
    for (int mt = 0; mt < 2; mt++)
#pragma unroll
        for (int nt = 0; nt < 8; nt++)
#pragma unroll
            for (int e = 0; e < 4; e++) acc[mt][nt][e] = 0.0f;

    const int lrow = tid >> 1;           // 0..127
    const int half = tid & 1;            // which 32-K half of the row
    const int rx = lrow & 7;
    const uint32_t rb = (uint32_t)lrow * 128u;

    const __half* Ap = g_xh + (size_t)(m0 + lrow) * DD + half * 32;
    const __half* Bp[2];
#pragma unroll
    for (int sp = 0; sp < 2; sp++)
        Bp[sp] = g_w1t[sp] + (size_t)(n0 + lrow) * DD + half * 32;

#define CP_CHUNK(c, st) do {                                                \
    const int _k0 = (c) * BK;                                               \
    const uint32_t _sb = sbase + SM_TILE + (st) * STAGE_SZ + rb;            \
    _Pragma("unroll")                                                       \
    for (int j = 0; j < 4; j++) {                                           \
        const uint32_t _co = (uint32_t)(((half * 4 + j) ^ rx) * 16);        \
        cp16(_sb + _co, Ap + _k0 + j * 8);                                  \
        cp16(_sb + 16384 + _co, Bp[0] + _k0 + j * 8);                       \
        cp16(_sb + 32768 + _co, Bp[1] + _k0 + j * 8);                       \
    }                                                                       \
} while (0)

    // Prologue: fill both stages
    CP_CHUNK(0, 0);
    CP_COMMIT();
    CP_CHUNK(1, 1);
    CP_COMMIT();

    for (int c = 0; c < NCH; c++) {
        const int st = c & 1;
        CP_WAIT1();              // stage st (group c) complete
        __syncthreads();

        const uint32_t abase = sbase + SM_TILE + st * STAGE_SZ;
#pragma unroll
        for (int ks = 0; ks < 4; ks++) {
            uint32_t a[2][4];        // [mtile][4]
            uint32_t bb[2][4][4];    // [split][npair][4]
            const int cc = ks * 2 + (lane >> 4);
#pragma unroll
            for (int mt = 0; mt < 2; mt++) {
                const int r = wm * 32 + mt * 16 + (lane & 15);
                const uint32_t addr = abase + r * 128 + ((cc ^ (r & 7)) * 16);
                ldm_x4(a[mt][0], a[mt][1], a[mt][2], a[mt][3], addr);
            }
#pragma unroll
            for (int sp = 0; sp < 2; sp++)
#pragma unroll
                for (int np = 0; np < 4; np++) {
                    const int r = wn * 64 + np * 16 + (lane & 15);
                    const uint32_t addr = abase + 16384 + sp * 16384
                                        + r * 128 + ((cc ^ (r & 7)) * 16);
                    ldm_x4(bb[sp][np][0], bb[sp][np][1], bb[sp][np][2], bb[sp][np][3], addr);
                }
#pragma unroll
            for (int mt = 0; mt < 2; mt++)
#pragma unroll
                for (int nt = 0; nt < 8; nt++) {
                    const int np = nt >> 1, sel = nt & 1;
                    mma_f16(acc[mt][nt], a[mt], bb[0][np][sel], bb[0][np][sel + 2]);
                    mma_f16(acc[mt][nt], a[mt], bb[1][np][sel], bb[1][np][sel + 2]);
                }
        }
        __syncthreads();         // all warps done with stage st
        if (c + 2 < NCH) {
            CP_CHUNK(c + 2, st);
            CP_COMMIT();
        } else {
            CP_COMMIT();         // keep group counting uniform
        }
    }

    // Epilogue: p = sum_cols relu(acc + b1) * w2, reduce across quads + wn.
#pragma unroll
    for (int mt = 0; mt < 2; mt++) {
        float p0 = 0.0f, p1 = 0.0f;
#pragma unroll
        for (int nt = 0; nt < 8; nt++) {
            const int cl = wn * 64 + nt * 8 + (lane & 3) * 2;
            const float w0 = w2s[cl], w1v = w2s[cl + 1];
            const float c0 = b1s[cl], c1 = b1s[cl + 1];
            p0 = fmaf(fmaxf(acc[mt][nt][0] + c0, 0.0f), w0, p0);
            p0 = fmaf(fmaxf(acc[mt][nt][1] + c1, 0.0f), w1v, p0);
            p1 = fmaf(fmaxf(acc[mt][nt][2] + c0, 0.0f), w0, p1);
            p1 = fmaf(fmaxf(acc[mt][nt][3] + c1, 0.0f), w1v, p1);
        }
        p0 += __shfl_xor_sync(0xffffffffu, p0, 1);
        p0 += __shfl_xor_sync(0xffffffffu, p0, 2);
        p1 += __shfl_xor_sync(0xffffffffu, p1, 1);
        p1 += __shfl_xor_sync(0xffffffffu, p1, 2);
        if ((lane & 3) == 0) {
            const int r0 = wm * 32 + mt * 16 + (lane >> 2);
            red[r0][wn] = p0;
            red[r0 + 8][wn] = p1;
        }
    }
    __syncthreads();
    if (tid < TM)
        g_yp[blockIdx.x][m0 + tid] = red[tid][0] + red[tid][1];
}

// ---------------------------------------------------------------------------
// Kernel B1: sum partials -> z, flag tokens within BAND of threshold.
// ---------------------------------------------------------------------------
__global__ __launch_bounds__(256, 8)
void zflag_kernel(const float* __restrict__ b2)
{
    const int t = blockIdx.x * 256 + threadIdx.x;
    const int b = t >> 12;
    const int s = t & (SQ - 1);
    if (s >= g_len[b]) { g_z[t] = 0.0f; return; }
    float z = g_yp[0][t] + g_yp[1][t] + g_yp[2][t] + g_yp[3][t] + b2[0];
    g_z[t] = z;
    if (fabsf(z - ZTHR) < BAND) {
        int i = atomicAdd(&g_nflag, 1);
        if (i < MAXFLAG) g_flag[i] = t;
    }
}

// ---------------------------------------------------------------------------
// Kernel R: exact fp32 recompute of flagged tokens' logits.
// One block (1024 thr) per flagged token: 8 k-groups x 128 h-quads.
// ---------------------------------------------------------------------------
__global__ __launch_bounds__(1024, 1)
void refine_kernel(const float* __restrict__ X,
                   const float* __restrict__ W1,
                   const float* __restrict__ b1,
                   const float* __restrict__ W2,
                   const float* __restrict__ b2)
{
    __shared__ float  xs[DD];           // 4KB
    __shared__ float4 part[8][128];     // 16KB
    __shared__ float  rr[4];
    const int tid = threadIdx.x;
    const int kg = tid >> 7;            // 0..7
    const int hq = tid & 127;           // h quad: h = hq*4..hq*4+3
    int n = g_nflag;
    if (n > MAXFLAG) n = MAXFLAG;

    for (int i = blockIdx.x; i < n; i += gridDim.x) {
        const int t = g_flag[i];
        if (tid < DD) xs[tid] = X[(size_t)t * DD + tid];
        __syncthreads();

        const float4* Wp = (const float4*)W1 + hq;
        float4 acc = make_float4(0.0f, 0.0f, 0.0f, 0.0f);
        const int k0 = kg * 128;
#pragma unroll 8
        for (int k = k0; k < k0 + 128; k++) {
            const float xk = xs[k];
            const float4 w = Wp[(size_t)k * (DH / 4)];
            acc.x = fmaf(xk, w.x, acc.x);
            acc.y = fmaf(xk, w.y, acc.y);
            acc.z = fmaf(xk, w.z, acc.z);
            acc.w = fmaf(xk, w.w, acc.w);
        }
        part[kg][hq] = acc;
        __syncthreads();

        if (tid < 128) {
            float4 s = part[0][tid];
#pragma unroll
            for (int g = 1; g < 8; g++) {
                const float4 q = part[g][tid];
                s.x += q.x; s.y += q.y; s.z += q.z; s.w += q.w;
            }
            const float4 bb = ((const float4*)b1)[tid];
            const float4 ww = ((const float4*)W2)[tid];
            float p;
            p  = fmaxf(s.x + bb.x, 0.0f) * ww.x;
            p += fmaxf(s.y + bb.y, 0.0f) * ww.y;
            p += fmaxf(s.z + bb.z, 0.0f) * ww.z;
            p += fmaxf(s.w + bb.w, 0.0f) * ww.w;
            p += __shfl_xor_sync(0xffffffffu, p, 16);
            p += __shfl_xor_sync(0xffffffffu, p, 8);
            p += __shfl_xor_sync(0xffffffffu, p, 4);
            p += __shfl_xor_sync(0xffffffffu, p, 2);
            p += __shfl_xor_sync(0xffffffffu, p, 1);
            if ((tid & 31) == 0) rr[tid >> 5] = p;
        }
        __syncthreads();
        if (tid == 0) g_z[t] = rr[0] + rr[1] + rr[2] + rr[3] + b2[0];
        __syncthreads();
    }
}

// ---------------------------------------------------------------------------
// Kernel B2: per-batch squash, max/adjust, compaction. Uses g_len.
// ---------------------------------------------------------------------------
__global__ __launch_bounds__(256, 1)
void gate_select_kernel(float* __restrict__ vpad_out, int write_vpad)
{
    const int b = blockIdx.x;
    const int tid = threadIdx.x;

    __shared__ float ysm[SQ];
    __shared__ float fred[256];
    __shared__ int   cnt[256];

    const int length = g_len[b];

    float mx = 0.0f;
    for (int s = tid; s < SQ; s += 256) {
        float y = (s < length)
                ? (1.0f + tanhf(10.0f * g_z[b * SQ + s])) * 0.5f : 0.0f;
        ysm[s] = y;
        mx = fmaxf(mx, y);
    }
    fred[tid] = mx;
    __syncthreads();
    for (int o = 128; o > 0; o >>= 1) {
        if (tid < o) fred[tid] = fmaxf(fred[tid], fred[tid + o]);
        __syncthreads();
    }
    const float adjust = fmaxf(0.0f, EPSV + THRESHOLD - fred[0]);
    __syncthreads();

    for (int s = tid; s < SQ; s += 256) {
        float yf = ysm[s] + adjust;
        ysm[s] = yf;
        g_yfin[b * SQ + s] = yf;
    }
    __syncthreads();

    const int CH = SQ / 256;
    const int base = tid * CH;
    int c = 0;
#pragma unroll
    for (int i = 0; i < CH; i++) {
        int s = base + i;
        c += (ysm[s] > THRESHOLD && s < length) ? 1 : 0;
    }
    cnt[tid] = c;
    __syncthreads();
    for (int o = 1; o < 256; o <<= 1) {
        int v = (tid >= o) ? cnt[tid - o] : 0;
        __syncthreads();
        cnt[tid] += v;
        __syncthreads();
    }
    int off = cnt[tid] - c;
#pragma unroll
    for (int i = 0; i < CH; i++) {
        int s = base + i;
        if (ysm[s] > THRESHOLD && s < length) g_idx[b][off++] = s;
    }
    const int nl = cnt[255];
    if (tid == 0) g_newlen[b] = nl;

    if (write_vpad) {
        for (int s = tid; s < SQ; s += 256)
            vpad_out[b * SQ + s] = (s >= nl) ? 1.0f : 0.0f;
    }
}

// ---------------------------------------------------------------------------
// Kernel C: scatter compacted rows.
// ---------------------------------------------------------------------------
__global__ __launch_bounds__(256, 4)
void scatter_kernel(const float* __restrict__ X, float* __restrict__ V)
{
    const int b = blockIdx.y;
    const int r = blockIdx.x;
    const int tid = threadIdx.x;
    const int nl = g_newlen[b];

    float4* vrow = (float4*)(V + ((size_t)b * SQ + r) * DD);
    if (r < nl) {
        const int s = g_idx[b][r];
        const float g = g_yfin[b * SQ + s];
        const float4* xrow = (const float4*)(X + ((size_t)b * SQ + s) * DD);
        float4 xv = xrow[tid];
        vrow[tid] = make_float4(xv.x * g, xv.y * g, xv.z * g, xv.w * g);
    } else {
        vrow[tid] = make_float4(0.0f, 0.0f, 0.0f, 0.0f);
    }
}

// ---------------------------------------------------------------------------
extern "C" void kernel_launch(void* const* d_in, const int* in_sizes, int n_in,
                              void* d_out, int out_size)
{
    const float*        x   = (const float*)d_in[0];
    const unsigned int* pad = (const unsigned int*)d_in[1];
    const float*        W1  = (const float*)d_in[2];
    const float*        b1  = (const float*)d_in[3];
    const float*        W2  = (const float*)d_in[4];
    const float*        b2  = (const float*)d_in[5];
    float* out = (float*)d_out;

    const long v_elems = (long)MM * DD;
    int write_vpad = (out_size > v_elems) ? 1 : 0;
    float* vpad = out + v_elems;

    cudaFuncSetAttribute(gemm_hmma,
                         cudaFuncAttributeMaxDynamicSharedMemorySize, SM_TOT);

    pad_len_kernel<<<BQ, 256>>>(pad);
    xconv_kernel<<<MM * DD / 1024, 256>>>(x);
    w1_split_kernel<<<dim3(DD / 32, DH / 32), dim3(32, 8)>>>(W1);
    gemm_hmma<<<dim3(NG, MM / TM), 256, SM_TOT>>>(b1, W2);
    zflag_kernel<<<MM / 256, 256>>>(b2);
    refine_kernel<<<64, 1024>>>(x, W1, b1, W2, b2);
    gate_select_kernel<<<BQ, 256>>>(vpad, write_vpad);
    scatter_kernel<<<dim3(SQ, BQ), 256>>>(x, out);
}

// round 12
// speedup vs baseline: 2.0026x; 1.3411x over previous
#include <cuda_runtime.h>
#include <cuda_fp16.h>
#include <cstdint>

// Problem shape (fixed by setup_inputs)
#define BQ 8
#define SQ 4096
#define DD 1024
#define DH 512
#define MM (BQ * SQ)           // 32768 tokens

#define THRESHOLD 0.1f
#define EPSV 1e-05f
#define ZTHR (-0.10986122886681098f)   // atanh(2*0.1-1)/10
#define BAND 6e-3f
#define MAXFLAG 8192

// GEMM tiling
#define TM 128                 // tokens per CTA
#define TN 128                 // hidden units per CTA
#define BK 64                  // K per chunk
#define NCH (DD / BK)          // 16
#define NG (DH / TN)           // 4 N-groups

// smem: per stage = A(16KB) + B(16KB) = 32KB; 2 stages = 64KB.
#define SM_B1    0             // 128 floats
#define SM_W2    512
#define SM_RED   1024          // float[128][2]
#define SM_TILE  2048
#define STAGE_SZ 32768
#define SM_TOT   (SM_TILE + 2 * STAGE_SZ)   // 67584

// Device scratch
__device__ __half g_xh[MM * DD];       // X rounded to fp16 (64MB)
__device__ __half g_w1h[DH * DD];      // transposed W1 fp16 [n*DD + k]
__device__ float g_yp[NG][MM];         // per-N-group partial logits
__device__ float g_z[MM];              // full logits (incl b2)
__device__ float g_yfin[MM];           // final gate values
__device__ int   g_len[BQ];            // valid lengths per batch
__device__ int   g_idx[BQ][SQ];
__device__ int   g_newlen[BQ];
__device__ int   g_nflag;
__device__ int   g_flag[MAXFLAG];

// ---------------------------------------------------------------------------
__device__ __forceinline__ uint32_t smem_u32(const void* p) {
    uint32_t a;
    asm("{ .reg .u64 t; cvta.to.shared.u64 t, %1; cvt.u32.u64 %0, t; }"
        : "=r"(a) : "l"(p));
    return a;
}
__device__ __forceinline__ void ldm_x4(uint32_t& r0, uint32_t& r1,
                                       uint32_t& r2, uint32_t& r3, uint32_t addr) {
    asm volatile("ldmatrix.sync.aligned.m8n8.x4.shared.b16 {%0,%1,%2,%3}, [%4];"
                 : "=r"(r0), "=r"(r1), "=r"(r2), "=r"(r3) : "r"(addr));
}
__device__ __forceinline__ void mma_f16(float* d, const uint32_t* a,
                                        uint32_t b0, uint32_t b1) {
    asm volatile(
        "mma.sync.aligned.m16n8k16.row.col.f32.f16.f16.f32 "
        "{%0,%1,%2,%3}, {%4,%5,%6,%7}, {%8,%9}, {%0,%1,%2,%3};"
        : "+f"(d[0]), "+f"(d[1]), "+f"(d[2]), "+f"(d[3])
        : "r"(a[0]), "r"(a[1]), "r"(a[2]), "r"(a[3]), "r"(b0), "r"(b1));
}
__device__ __forceinline__ void cp16(uint32_t dst, const void* src) {
    asm volatile("cp.async.cg.shared.global [%0], [%1], 16;"
                 :: "r"(dst), "l"(src));
}
#define CP_COMMIT() asm volatile("cp.async.commit_group;" ::: "memory")
#define CP_WAIT1()  asm volatile("cp.async.wait_group 1;" ::: "memory")

// ---------------------------------------------------------------------------
// Kernel P: per-batch valid length from pad (4-byte elems, nonzero = padded).
// ---------------------------------------------------------------------------
__global__ __launch_bounds__(256, 4)
void pad_len_kernel(const unsigned int* __restrict__ pad)
{
    __shared__ int ired[256];
    const int b = blockIdx.x;
    const int tid = threadIdx.x;
    if (b == 0 && tid == 0) g_nflag = 0;
    int lc = 0;
    for (int s = tid; s < SQ; s += 256)
        lc += (pad[b * SQ + s] == 0u) ? 1 : 0;
    ired[tid] = lc;
    __syncthreads();
    for (int o = 128; o > 0; o >>= 1) {
        if (tid < o) ired[tid] += ired[tid + o];
        __syncthreads();
    }
    if (tid == 0) g_len[b] = ired[0];
}

// ---------------------------------------------------------------------------
// Kernel X: convert X fp32 -> fp16 (round-to-nearest).
// ---------------------------------------------------------------------------
__global__ __launch_bounds__(256, 8)
void xconv_kernel(const float* __restrict__ X)
{
    const int i = blockIdx.x * 256 + threadIdx.x;     // per 4 elements
    const float4 v = ((const float4*)X)[i];
    __half2 h0 = __floats2half2_rn(v.x, v.y);
    __half2 h1 = __floats2half2_rn(v.z, v.w);
    uint2 o;
    o.x = *(uint32_t*)&h0;
    o.y = *(uint32_t*)&h1;
    ((uint2*)g_xh)[i] = o;
}

// ---------------------------------------------------------------------------
// Kernel 0: coalesced tiled transpose + fp16 round of W1.
// ---------------------------------------------------------------------------
__global__ __launch_bounds__(256, 6)
void w1_split_kernel(const float* __restrict__ W1) {
    __shared__ float tile[32][33];
    const int k0 = blockIdx.x * 32;
    const int n0 = blockIdx.y * 32;
    const int tx = threadIdx.x;   // 0..31
    const int ty = threadIdx.y;   // 0..7

#pragma unroll
    for (int j = 0; j < 4; j++) {
        const int k = k0 + ty + j * 8;
        tile[ty + j * 8][tx] = W1[(size_t)k * DH + n0 + tx];
    }
    __syncthreads();

#pragma unroll
    for (int j = 0; j < 4; j++) {
        const int n = n0 + ty + j * 8;
        g_w1h[(size_t)n * DD + k0 + tx] = __float2half_rn(tile[tx][ty + j * 8]);
    }
}

// ---------------------------------------------------------------------------
// Kernel A: pure fp16 HMMA GEMM, cp.async pipeline, 2 stages, 2 CTAs/SM.
// Padded M-tiles skipped; near-threshold tokens refined in fp32 later.
// ---------------------------------------------------------------------------
__global__ __launch_bounds__(256, 2)
void gemm_hmma(const float* __restrict__ b1,
               const float* __restrict__ W2)
{
    extern __shared__ char smem[];
    const uint32_t sbase = smem_u32(smem);
    const int tid = threadIdx.x;
    const int wid = tid >> 5;
    const int lane = tid & 31;
    const int wm = wid & 3;          // M quadrant (32 rows)
    const int wn = wid >> 2;         // N half (64 cols)
    const int n0 = blockIdx.x * TN;
    const int m0 = blockIdx.y * TM;

    // Early exit: tile fully in trailing padding -> logits never read.
    const int bq = m0 >> 12;
    const int s0 = m0 & (SQ - 1);
    if (s0 >= g_len[bq]) return;

    float* b1s = (float*)(smem + SM_B1);
    float* w2s = (float*)(smem + SM_W2);
    float (*red)[2] = (float(*)[2])(smem + SM_RED);
    if (tid < TN) {
        b1s[tid] = b1[n0 + tid];
        w2s[tid] = W2[n0 + tid];
    }

    float acc[2][8][4];
#pragma unroll
    for (int mt = 0; mt < 2; mt++)
#pragma unroll
        for (int nt = 0; nt < 8; nt++)
#pragma unroll
            for (int e = 0; e < 4; e++) acc[mt][nt][e] = 0.0f;

    const int lrow = tid >> 1;           // 0..127
    const int half = tid & 1;            // which 32-K half of the row
    const int rx = lrow & 7;
    const uint32_t rb = (uint32_t)lrow * 128u;

    const __half* Ap = g_xh + (size_t)(m0 + lrow) * DD + half * 32;
    const __half* Bp = g_w1h + (size_t)(n0 + lrow) * DD + half * 32;

#define CP_CHUNK(c, st) do {                                                \
    const int _k0 = (c) * BK;                                               \
    const uint32_t _sb = sbase + SM_TILE + (st) * STAGE_SZ + rb;            \
    _Pragma("unroll")                                                       \
    for (int j = 0; j < 4; j++) {                                           \
        const uint32_t _co = (uint32_t)(((half * 4 + j) ^ rx) * 16);        \
        cp16(_sb + _co, Ap + _k0 + j * 8);                                  \
        cp16(_sb + 16384 + _co, Bp + _k0 + j * 8);                          \
    }                                                                       \
} while (0)

    // Prologue: fill both stages
    CP_CHUNK(0, 0);
    CP_COMMIT();
    CP_CHUNK(1, 1);
    CP_COMMIT();

    for (int c = 0; c < NCH; c++) {
        const int st = c & 1;
        CP_WAIT1();              // stage st (group c) complete
        __syncthreads();

        const uint32_t abase = sbase + SM_TILE + st * STAGE_SZ;
#pragma unroll
        for (int ks = 0; ks < 4; ks++) {
            uint32_t a[2][4];        // [mtile][4]
            uint32_t bb[4][4];       // [npair][4]
            const int cc = ks * 2 + (lane >> 4);
#pragma unroll
            for (int mt = 0; mt < 2; mt++) {
                const int r = wm * 32 + mt * 16 + (lane & 15);
                const uint32_t addr = abase + r * 128 + ((cc ^ (r & 7)) * 16);
                ldm_x4(a[mt][0], a[mt][1], a[mt][2], a[mt][3], addr);
            }
#pragma unroll
            for (int np = 0; np < 4; np++) {
                const int r = wn * 64 + np * 16 + (lane & 15);
                const uint32_t addr = abase + 16384
                                    + r * 128 + ((cc ^ (r & 7)) * 16);
                ldm_x4(bb[np][0], bb[np][1], bb[np][2], bb[np][3], addr);
            }
#pragma unroll
            for (int mt = 0; mt < 2; mt++)
#pragma unroll
                for (int nt = 0; nt < 8; nt++) {
                    const int np = nt >> 1, sel = nt & 1;
                    mma_f16(acc[mt][nt], a[mt], bb[np][sel], bb[np][sel + 2]);
                }
        }
        __syncthreads();         // all warps done with stage st
        if (c + 2 < NCH) {
            CP_CHUNK(c + 2, st);
            CP_COMMIT();
        } else {
            CP_COMMIT();         // keep group counting uniform
        }
    }

    // Epilogue: p = sum_cols relu(acc + b1) * w2, reduce across quads + wn.
#pragma unroll
    for (int mt = 0; mt < 2; mt++) {
        float p0 = 0.0f, p1 = 0.0f;
#pragma unroll
        for (int nt = 0; nt < 8; nt++) {
            const int cl = wn * 64 + nt * 8 + (lane & 3) * 2;
            const float w0 = w2s[cl], w1v = w2s[cl + 1];
            const float c0 = b1s[cl], c1 = b1s[cl + 1];
            p0 = fmaf(fmaxf(acc[mt][nt][0] + c0, 0.0f), w0, p0);
            p0 = fmaf(fmaxf(acc[mt][nt][1] + c1, 0.0f), w1v, p0);
            p1 = fmaf(fmaxf(acc[mt][nt][2] + c0, 0.0f), w0, p1);
            p1 = fmaf(fmaxf(acc[mt][nt][3] + c1, 0.0f), w1v, p1);
        }
        p0 += __shfl_xor_sync(0xffffffffu, p0, 1);
        p0 += __shfl_xor_sync(0xffffffffu, p0, 2);
        p1 += __shfl_xor_sync(0xffffffffu, p1, 1);
        p1 += __shfl_xor_sync(0xffffffffu, p1, 2);
        if ((lane & 3) == 0) {
            const int r0 = wm * 32 + mt * 16 + (lane >> 2);
            red[r0][wn] = p0;
            red[r0 + 8][wn] = p1;
        }
    }
    __syncthreads();
    if (tid < TM)
        g_yp[blockIdx.x][m0 + tid] = red[tid][0] + red[tid][1];
}

// ---------------------------------------------------------------------------
// Kernel B1: sum partials -> z, flag tokens within BAND of threshold.
// ---------------------------------------------------------------------------
__global__ __launch_bounds__(256, 8)
void zflag_kernel(const float* __restrict__ b2)
{
    const int t = blockIdx.x * 256 + threadIdx.x;
    const int b = t >> 12;
    const int s = t & (SQ - 1);
    if (s >= g_len[b]) { g_z[t] = 0.0f; return; }
    float z = g_yp[0][t] + g_yp[1][t] + g_yp[2][t] + g_yp[3][t] + b2[0];
    g_z[t] = z;
    if (fabsf(z - ZTHR) < BAND) {
        int i = atomicAdd(&g_nflag, 1);
        if (i < MAXFLAG) g_flag[i] = t;
    }
}

// ---------------------------------------------------------------------------
// Kernel R: exact fp32 recompute of flagged tokens' logits.
// One block (1024 thr) per flagged token: 8 k-groups x 128 h-quads.
// ---------------------------------------------------------------------------
__global__ __launch_bounds__(1024, 1)
void refine_kernel(const float* __restrict__ X,
                   const float* __restrict__ W1,
                   const float* __restrict__ b1,
                   const float* __restrict__ W2,
                   const float* __restrict__ b2)
{
    __shared__ float  xs[DD];           // 4KB
    __shared__ float4 part[8][128];     // 16KB
    __shared__ float  rr[4];
    const int tid = threadIdx.x;
    const int kg = tid >> 7;            // 0..7
    const int hq = tid & 127;           // h quad: h = hq*4..hq*4+3
    int n = g_nflag;
    if (n > MAXFLAG) n = MAXFLAG;

    for (int i = blockIdx.x; i < n; i += gridDim.x) {
        const int t = g_flag[i];
        if (tid < DD) xs[tid] = X[(size_t)t * DD + tid];
        __syncthreads();

        const float4* Wp = (const float4*)W1 + hq;
        float4 acc = make_float4(0.0f, 0.0f, 0.0f, 0.0f);
        const int k0 = kg * 128;
#pragma unroll 8
        for (int k = k0; k < k0 + 128; k++) {
            const float xk = xs[k];
            const float4 w = Wp[(size_t)k * (DH / 4)];
            acc.x = fmaf(xk, w.x, acc.x);
            acc.y = fmaf(xk, w.y, acc.y);
            acc.z = fmaf(xk, w.z, acc.z);
            acc.w = fmaf(xk, w.w, acc.w);
        }
        part[kg][hq] = acc;
        __syncthreads();

        if (tid < 128) {
            float4 s = part[0][tid];
#pragma unroll
            for (int g = 1; g < 8; g++) {
                const float4 q = part[g][tid];
                s.x += q.x; s.y += q.y; s.z += q.z; s.w += q.w;
            }
            const float4 bb = ((const float4*)b1)[tid];
            const float4 ww = ((const float4*)W2)[tid];
            float p;
            p  = fmaxf(s.x + bb.x, 0.0f) * ww.x;
            p += fmaxf(s.y + bb.y, 0.0f) * ww.y;
            p += fmaxf(s.z + bb.z, 0.0f) * ww.z;
            p += fmaxf(s.w + bb.w, 0.0f) * ww.w;
            p += __shfl_xor_sync(0xffffffffu, p, 16);
            p += __shfl_xor_sync(0xffffffffu, p, 8);
            p += __shfl_xor_sync(0xffffffffu, p, 4);
            p += __shfl_xor_sync(0xffffffffu, p, 2);
            p += __shfl_xor_sync(0xffffffffu, p, 1);
            if ((tid & 31) == 0) rr[tid >> 5] = p;
        }
        __syncthreads();
        if (tid == 0) g_z[t] = rr[0] + rr[1] + rr[2] + rr[3] + b2[0];
        __syncthreads();
    }
}

// ---------------------------------------------------------------------------
// Kernel B2: per-batch squash, max/adjust, compaction. Uses g_len.
// ---------------------------------------------------------------------------
__global__ __launch_bounds__(256, 1)
void gate_select_kernel(float* __restrict__ vpad_out, int write_vpad)
{
    const int b = blockIdx.x;
    const int tid = threadIdx.x;

    __shared__ float ysm[SQ];
    __shared__ float fred[256];
    __shared__ int   cnt[256];

    const int length = g_len[b];

    float mx = 0.0f;
    for (int s = tid; s < SQ; s += 256) {
        float y = (s < length)
                ? (1.0f + tanhf(10.0f * g_z[b * SQ + s])) * 0.5f : 0.0f;
        ysm[s] = y;
        mx = fmaxf(mx, y);
    }
    fred[tid] = mx;
    __syncthreads();
    for (int o = 128; o > 0; o >>= 1) {
        if (tid < o) fred[tid] = fmaxf(fred[tid], fred[tid + o]);
        __syncthreads();
    }
    const float adjust = fmaxf(0.0f, EPSV + THRESHOLD - fred[0]);
    __syncthreads();

    for (int s = tid; s < SQ; s += 256) {
        float yf = ysm[s] + adjust;
        ysm[s] = yf;
        g_yfin[b * SQ + s] = yf;
    }
    __syncthreads();

    const int CH = SQ / 256;
    const int base = tid * CH;
    int c = 0;
#pragma unroll
    for (int i = 0; i < CH; i++) {
        int s = base + i;
        c += (ysm[s] > THRESHOLD && s < length) ? 1 : 0;
    }
    cnt[tid] = c;
    __syncthreads();
    for (int o = 1; o < 256; o <<= 1) {
        int v = (tid >= o) ? cnt[tid - o] : 0;
        __syncthreads();
        cnt[tid] += v;
        __syncthreads();
    }
    int off = cnt[tid] - c;
#pragma unroll
    for (int i = 0; i < CH; i++) {
        int s = base + i;
        if (ysm[s] > THRESHOLD && s < length) g_idx[b][off++] = s;
    }
    const int nl = cnt[255];
    if (tid == 0) g_newlen[b] = nl;

    if (write_vpad) {
        for (int s = tid; s < SQ; s += 256)
            vpad_out[b * SQ + s] = (s >= nl) ? 1.0f : 0.0f;
    }
}

// ---------------------------------------------------------------------------
// Kernel C: scatter compacted rows.
// ---------------------------------------------------------------------------
__global__ __launch_bounds__(256, 4)
void scatter_kernel(const float* __restrict__ X, float* __restrict__ V)
{
    const int b = blockIdx.y;
    const int r = blockIdx.x;
    const int tid = threadIdx.x;
    const int nl = g_newlen[b];

    float4* vrow = (float4*)(V + ((size_t)b * SQ + r) * DD);
    if (r < nl) {
        const int s = g_idx[b][r];
        const float g = g_yfin[b * SQ + s];
        const float4* xrow = (const float4*)(X + ((size_t)b * SQ + s) * DD);
        float4 xv = xrow[tid];
        vrow[tid] = make_float4(xv.x * g, xv.y * g, xv.z * g, xv.w * g);
    } else {
        vrow[tid] = make_float4(0.0f, 0.0f, 0.0f, 0.0f);
    }
}

// ---------------------------------------------------------------------------
extern "C" void kernel_launch(void* const* d_in, const int* in_sizes, int n_in,
                              void* d_out, int out_size)
{
    const float*        x   = (const float*)d_in[0];
    const unsigned int* pad = (const unsigned int*)d_in[1];
    const float*        W1  = (const float*)d_in[2];
    const float*        b1  = (const float*)d_in[3];
    const float*        W2  = (const float*)d_in[4];
    const float*        b2  = (const float*)d_in[5];
    float* out = (float*)d_out;

    const long v_elems = (long)MM * DD;
    int write_vpad = (out_size > v_elems) ? 1 : 0;
    float* vpad = out + v_elems;

    cudaFuncSetAttribute(gemm_hmma,
                         cudaFuncAttributeMaxDynamicSharedMemorySize, SM_TOT);

    pad_len_kernel<<<BQ, 256>>>(pad);
    xconv_kernel<<<MM * DD / 1024, 256>>>(x);
    w1_split_kernel<<<dim3(DD / 32, DH / 32), dim3(32, 8)>>>(W1);
    gemm_hmma<<<dim3(NG, MM / TM), 256, SM_TOT>>>(b1, W2);
    zflag_kernel<<<MM / 256, 256>>>(b2);
    refine_kernel<<<128, 1024>>>(x, W1, b1, W2, b2);
    gate_select_kernel<<<BQ, 256>>>(vpad, write_vpad);
    scatter_kernel<<<dim3(SQ, BQ), 256>>>(x, out);
}

// round 13
// speedup vs baseline: 2.0687x; 1.0330x over previous
#include <cuda_runtime.h>
#include <cuda_fp16.h>
#include <cstdint>

// Problem shape (fixed by setup_inputs)
#define BQ 8
#define SQ 4096
#define DD 1024
#define DH 512
#define MM (BQ * SQ)           // 32768 tokens

#define THRESHOLD 0.1f
#define EPSV 1e-05f
#define ZTHR (-0.10986122886681098f)   // atanh(2*0.1-1)/10
#define BAND 6e-3f
#define MAXFLAG 8192

// GEMM tiling
#define TM 128                 // tokens per CTA
#define TN 128                 // hidden units per CTA
#define BK 64                  // K per chunk
#define NCH (DD / BK)          // 16
#define NG (DH / TN)           // 4 N-groups

// smem: per stage = A(16KB) + B(16KB) = 32KB; 3 stages = 96KB.
#define SM_B1    0             // 128 floats
#define SM_W2    512
#define SM_RED   1024          // float[128][2]
#define SM_TILE  2048
#define STAGE_SZ 32768
#define SM_TOT   (SM_TILE + 3 * STAGE_SZ)   // 100352

// Device scratch
__device__ __half g_xh[MM * DD];       // X rounded to fp16 (64MB)
__device__ __half g_w1h[DH * DD];      // transposed W1 fp16 [n*DD + k]
__device__ float g_yp[NG][MM];         // per-N-group partial logits
__device__ float g_z[MM];              // full logits (incl b2)
__device__ float g_yfin[MM];           // final gate values
__device__ int   g_len[BQ];            // valid lengths per batch
__device__ int   g_idx[BQ][SQ];
__device__ int   g_newlen[BQ];
__device__ int   g_nflag;
__device__ int   g_flag[MAXFLAG];

// ---------------------------------------------------------------------------
__device__ __forceinline__ uint32_t smem_u32(const void* p) {
    uint32_t a;
    asm("{ .reg .u64 t; cvta.to.shared.u64 t, %1; cvt.u32.u64 %0, t; }"
        : "=r"(a) : "l"(p));
    return a;
}
__device__ __forceinline__ void ldm_x4(uint32_t& r0, uint32_t& r1,
                                       uint32_t& r2, uint32_t& r3, uint32_t addr) {
    asm volatile("ldmatrix.sync.aligned.m8n8.x4.shared.b16 {%0,%1,%2,%3}, [%4];"
                 : "=r"(r0), "=r"(r1), "=r"(r2), "=r"(r3) : "r"(addr));
}
__device__ __forceinline__ void mma_f16(float* d, const uint32_t* a,
                                        uint32_t b0, uint32_t b1) {
    asm volatile(
        "mma.sync.aligned.m16n8k16.row.col.f32.f16.f16.f32 "
        "{%0,%1,%2,%3}, {%4,%5,%6,%7}, {%8,%9}, {%0,%1,%2,%3};"
        : "+f"(d[0]), "+f"(d[1]), "+f"(d[2]), "+f"(d[3])
        : "r"(a[0]), "r"(a[1]), "r"(a[2]), "r"(a[3]), "r"(b0), "r"(b1));
}
__device__ __forceinline__ void cp16(uint32_t dst, const void* src) {
    asm volatile("cp.async.cg.shared.global [%0], [%1], 16;"
                 :: "r"(dst), "l"(src));
}
#define CP_COMMIT() asm volatile("cp.async.commit_group;" ::: "memory")
#define CP_WAIT2()  asm volatile("cp.async.wait_group 2;" ::: "memory")

// ---------------------------------------------------------------------------
// Kernel P: per-batch valid length from pad (4-byte elems, nonzero = padded).
// ---------------------------------------------------------------------------
__global__ __launch_bounds__(256, 4)
void pad_len_kernel(const unsigned int* __restrict__ pad)
{
    __shared__ int ired[256];
    const int b = blockIdx.x;
    const int tid = threadIdx.x;
    if (b == 0 && tid == 0) g_nflag = 0;
    int lc = 0;
    for (int s = tid; s < SQ; s += 256)
        lc += (pad[b * SQ + s] == 0u) ? 1 : 0;
    ired[tid] = lc;
    __syncthreads();
    for (int o = 128; o > 0; o >>= 1) {
        if (tid < o) ired[tid] += ired[tid + o];
        __syncthreads();
    }
    if (tid == 0) g_len[b] = ired[0];
}

// ---------------------------------------------------------------------------
// Kernel X: convert X fp32 -> fp16, one block per token; padded tokens
// skipped (their logits are never observable; gemm rows are M-independent).
// ---------------------------------------------------------------------------
__global__ __launch_bounds__(256, 8)
void xconv_kernel(const float* __restrict__ X)
{
    const int t = blockIdx.x;
    const int s = t & (SQ - 1);
    if (s >= g_len[t >> 12]) return;
    const int i = t * 256 + threadIdx.x;   // per 4 elements
    const float4 v = ((const float4*)X)[i];
    __half2 h0 = __floats2half2_rn(v.x, v.y);
    __half2 h1 = __floats2half2_rn(v.z, v.w);
    uint2 o;
    o.x = *(uint32_t*)&h0;
    o.y = *(uint32_t*)&h1;
    ((uint2*)g_xh)[i] = o;
}

// ---------------------------------------------------------------------------
// Kernel 0: coalesced tiled transpose + fp16 round of W1.
// ---------------------------------------------------------------------------
__global__ __launch_bounds__(256, 6)
void w1_split_kernel(const float* __restrict__ W1) {
    __shared__ float tile[32][33];
    const int k0 = blockIdx.x * 32;
    const int n0 = blockIdx.y * 32;
    const int tx = threadIdx.x;   // 0..31
    const int ty = threadIdx.y;   // 0..7

#pragma unroll
    for (int j = 0; j < 4; j++) {
        const int k = k0 + ty + j * 8;
        tile[ty + j * 8][tx] = W1[(size_t)k * DH + n0 + tx];
    }
    __syncthreads();

#pragma unroll
    for (int j = 0; j < 4; j++) {
        const int n = n0 + ty + j * 8;
        g_w1h[(size_t)n * DD + k0 + tx] = __float2half_rn(tile[tx][ty + j * 8]);
    }
}

// ---------------------------------------------------------------------------
// Kernel A: pure fp16 HMMA GEMM, 3-stage cp.async pipeline, 2 CTAs/SM.
// Padded M-tiles skipped; near-threshold tokens refined in fp32 later.
// ---------------------------------------------------------------------------
__global__ __launch_bounds__(256, 2)
void gemm_hmma(const float* __restrict__ b1,
               const float* __restrict__ W2)
{
    extern __shared__ char smem[];
    const uint32_t sbase = smem_u32(smem);
    const int tid = threadIdx.x;
    const int wid = tid >> 5;
    const int lane = tid & 31;
    const int wm = wid & 3;          // M quadrant (32 rows)
    const int wn = wid >> 2;         // N half (64 cols)
    const int n0 = blockIdx.x * TN;
    const int m0 = blockIdx.y * TM;

    // Early exit: tile fully in trailing padding -> logits never read.
    const int bq = m0 >> 12;
    const int s0 = m0 & (SQ - 1);
    if (s0 >= g_len[bq]) return;

    float* b1s = (float*)(smem + SM_B1);
    float* w2s = (float*)(smem + SM_W2);
    float (*red)[2] = (float(*)[2])(smem + SM_RED);
    if (tid < TN) {
        b1s[tid] = b1[n0 + tid];
        w2s[tid] = W2[n0 + tid];
    }

    float acc[2][8][4];
#pragma unroll
    for (int mt = 0; mt < 2; mt++)
#pragma unroll
        for (int nt = 0; nt < 8; nt++)
#pragma unroll
            for (int e = 0; e < 4; e++) acc[mt][nt][e] = 0.0f;

    const int lrow = tid >> 1;           // 0..127
    const int half = tid & 1;            // which 32-K half of the row
    const int rx = lrow & 7;
    const uint32_t rb = (uint32_t)lrow * 128u;

    const __half* Ap = g_xh + (size_t)(m0 + lrow) * DD + half * 32;
    const __half* Bp = g_w1h + (size_t)(n0 + lrow) * DD + half * 32;

#define CP_CHUNK(c, st) do {                                                \
    const int _k0 = (c) * BK;                                               \
    const uint32_t _sb = sbase + SM_TILE + (st) * STAGE_SZ + rb;            \
    _Pragma("unroll")                                                       \
    for (int j = 0; j < 4; j++) {                                           \
        const uint32_t _co = (uint32_t)(((half * 4 + j) ^ rx) * 16);        \
        cp16(_sb + _co, Ap + _k0 + j * 8);                                  \
        cp16(_sb + 16384 + _co, Bp + _k0 + j * 8);                          \
    }                                                                       \
} while (0)

    // Prologue: fill all 3 stages
    CP_CHUNK(0, 0);
    CP_COMMIT();
    CP_CHUNK(1, 1);
    CP_COMMIT();
    CP_CHUNK(2, 2);
    CP_COMMIT();

    int st = 0;
    for (int c = 0; c < NCH; c++) {
        CP_WAIT2();              // oldest group (stage st, chunk c) complete
        __syncthreads();

        const uint32_t abase = sbase + SM_TILE + st * STAGE_SZ;
#pragma unroll
        for (int ks = 0; ks < 4; ks++) {
            uint32_t a[2][4];        // [mtile][4]
            uint32_t bb[4][4];       // [npair][4]
            const int cc = ks * 2 + (lane >> 4);
#pragma unroll
            for (int mt = 0; mt < 2; mt++) {
                const int r = wm * 32 + mt * 16 + (lane & 15);
                const uint32_t addr = abase + r * 128 + ((cc ^ (r & 7)) * 16);
                ldm_x4(a[mt][0], a[mt][1], a[mt][2], a[mt][3], addr);
            }
#pragma unroll
            for (int np = 0; np < 4; np++) {
                const int r = wn * 64 + np * 16 + (lane & 15);
                const uint32_t addr = abase + 16384
                                    + r * 128 + ((cc ^ (r & 7)) * 16);
                ldm_x4(bb[np][0], bb[np][1], bb[np][2], bb[np][3], addr);
            }
#pragma unroll
            for (int mt = 0; mt < 2; mt++)
#pragma unroll
                for (int nt = 0; nt < 8; nt++) {
                    const int np = nt >> 1, sel = nt & 1;
                    mma_f16(acc[mt][nt], a[mt], bb[np][sel], bb[np][sel + 2]);
                }
        }
        __syncthreads();         // all warps done with stage st
        if (c + 3 < NCH) {
            CP_CHUNK(c + 3, st);
            CP_COMMIT();
        } else {
            CP_COMMIT();         // keep group counting uniform
        }
        st = (st == 2) ? 0 : st + 1;
    }

    // Epilogue: p = sum_cols relu(acc + b1) * w2, reduce across quads + wn.
#pragma unroll
    for (int mt = 0; mt < 2; mt++) {
        float p0 = 0.0f, p1 = 0.0f;
#pragma unroll
        for (int nt = 0; nt < 8; nt++) {
            const int cl = wn * 64 + nt * 8 + (lane & 3) * 2;
            const float w0 = w2s[cl], w1v = w2s[cl + 1];
            const float c0 = b1s[cl], c1 = b1s[cl + 1];
            p0 = fmaf(fmaxf(acc[mt][nt][0] + c0, 0.0f), w0, p0);
            p0 = fmaf(fmaxf(acc[mt][nt][1] + c1, 0.0f), w1v, p0);
            p1 = fmaf(fmaxf(acc[mt][nt][2] + c0, 0.0f), w0, p1);
            p1 = fmaf(fmaxf(acc[mt][nt][3] + c1, 0.0f), w1v, p1);
        }
        p0 += __shfl_xor_sync(0xffffffffu, p0, 1);
        p0 += __shfl_xor_sync(0xffffffffu, p0, 2);
        p1 += __shfl_xor_sync(0xffffffffu, p1, 1);
        p1 += __shfl_xor_sync(0xffffffffu, p1, 2);
        if ((lane & 3) == 0) {
            const int r0 = wm * 32 + mt * 16 + (lane >> 2);
            red[r0][wn] = p0;
            red[r0 + 8][wn] = p1;
        }
    }
    __syncthreads();
    if (tid < TM)
        g_yp[blockIdx.x][m0 + tid] = red[tid][0] + red[tid][1];
}

// ---------------------------------------------------------------------------
// Kernel B1: sum partials -> z, flag tokens within BAND of threshold.
// ---------------------------------------------------------------------------
__global__ __launch_bounds__(256, 8)
void zflag_kernel(const float* __restrict__ b2)
{
    const int t = blockIdx.x * 256 + threadIdx.x;
    const int b = t >> 12;
    const int s = t & (SQ - 1);
    if (s >= g_len[b]) { g_z[t] = 0.0f; return; }
    float z = g_yp[0][t] + g_yp[1][t] + g_yp[2][t] + g_yp[3][t] + b2[0];
    g_z[t] = z;
    if (fabsf(z - ZTHR) < BAND) {
        int i = atomicAdd(&g_nflag, 1);
        if (i < MAXFLAG) g_flag[i] = t;
    }
}

// ---------------------------------------------------------------------------
// Kernel R: exact fp32 recompute of flagged tokens' logits.
// One block (1024 thr) per flagged token: 8 k-groups x 128 h-quads.
// ---------------------------------------------------------------------------
__global__ __launch_bounds__(1024, 1)
void refine_kernel(const float* __restrict__ X,
                   const float* __restrict__ W1,
                   const float* __restrict__ b1,
                   const float* __restrict__ W2,
                   const float* __restrict__ b2)
{
    __shared__ float  xs[DD];           // 4KB
    __shared__ float4 part[8][128];     // 16KB
    __shared__ float  rr[4];
    const int tid = threadIdx.x;
    const int kg = tid >> 7;            // 0..7
    const int hq = tid & 127;           // h quad: h = hq*4..hq*4+3
    int n = g_nflag;
    if (n > MAXFLAG) n = MAXFLAG;

    for (int i = blockIdx.x; i < n; i += gridDim.x) {
        const int t = g_flag[i];
        if (tid < DD) xs[tid] = X[(size_t)t * DD + tid];
        __syncthreads();

        const float4* Wp = (const float4*)W1 + hq;
        float4 acc = make_float4(0.0f, 0.0f, 0.0f, 0.0f);
        const int k0 = kg * 128;
#pragma unroll 8
        for (int k = k0; k < k0 + 128; k++) {
            const float xk = xs[k];
            const float4 w = Wp[(size_t)k * (DH / 4)];
            acc.x = fmaf(xk, w.x, acc.x);
            acc.y = fmaf(xk, w.y, acc.y);
            acc.z = fmaf(xk, w.z, acc.z);
            acc.w = fmaf(xk, w.w, acc.w);
        }
        part[kg][hq] = acc;
        __syncthreads();

        if (tid < 128) {
            float4 s = part[0][tid];
#pragma unroll
            for (int g = 1; g < 8; g++) {
                const float4 q = part[g][tid];
                s.x += q.x; s.y += q.y; s.z += q.z; s.w += q.w;
            }
            const float4 bb = ((const float4*)b1)[tid];
            const float4 ww = ((const float4*)W2)[tid];
            float p;
            p  = fmaxf(s.x + bb.x, 0.0f) * ww.x;
            p += fmaxf(s.y + bb.y, 0.0f) * ww.y;
            p += fmaxf(s.z + bb.z, 0.0f) * ww.z;
            p += fmaxf(s.w + bb.w, 0.0f) * ww.w;
            p += __shfl_xor_sync(0xffffffffu, p, 16);
            p += __shfl_xor_sync(0xffffffffu, p, 8);
            p += __shfl_xor_sync(0xffffffffu, p, 4);
            p += __shfl_xor_sync(0xffffffffu, p, 2);
            p += __shfl_xor_sync(0xffffffffu, p, 1);
            if ((tid & 31) == 0) rr[tid >> 5] = p;
        }
        __syncthreads();
        if (tid == 0) g_z[t] = rr[0] + rr[1] + rr[2] + rr[3] + b2[0];
        __syncthreads();
    }
}

// ---------------------------------------------------------------------------
// Kernel B2: per-batch squash, max/adjust, compaction. Uses g_len.
// ---------------------------------------------------------------------------
__global__ __launch_bounds__(256, 1)
void gate_select_kernel(float* __restrict__ vpad_out, int write_vpad)
{
    const int b = blockIdx.x;
    const int tid = threadIdx.x;

    __shared__ float ysm[SQ];
    __shared__ float fred[256];
    __shared__ int   cnt[256];

    const int length = g_len[b];

    float mx = 0.0f;
    for (int s = tid; s < SQ; s += 256) {
        float y = (s < length)
                ? (1.0f + tanhf(10.0f * g_z[b * SQ + s])) * 0.5f : 0.0f;
        ysm[s] = y;
        mx = fmaxf(mx, y);
    }
    fred[tid] = mx;
    __syncthreads();
    for (int o = 128; o > 0; o >>= 1) {
        if (tid < o) fred[tid] = fmaxf(fred[tid], fred[tid + o]);
        __syncthreads();
    }
    const float adjust = fmaxf(0.0f, EPSV + THRESHOLD - fred[0]);
    __syncthreads();

    for (int s = tid; s < SQ; s += 256) {
        float yf = ysm[s] + adjust;
        ysm[s] = yf;
        g_yfin[b * SQ + s] = yf;
    }
    __syncthreads();

    const int CH = SQ / 256;
    const int base = tid * CH;
    int c = 0;
#pragma unroll
    for (int i = 0; i < CH; i++) {
        int s = base + i;
        c += (ysm[s] > THRESHOLD && s < length) ? 1 : 0;
    }
    cnt[tid] = c;
    __syncthreads();
    for (int o = 1; o < 256; o <<= 1) {
        int v = (tid >= o) ? cnt[tid - o] : 0;
        __syncthreads();
        cnt[tid] += v;
        __syncthreads();
    }
    int off = cnt[tid] - c;
#pragma unroll
    for (int i = 0; i < CH; i++) {
        int s = base + i;
        if (ysm[s] > THRESHOLD && s < length) g_idx[b][off++] = s;
    }
    const int nl = cnt[255];
    if (tid == 0) g_newlen[b] = nl;

    if (write_vpad) {
        for (int s = tid; s < SQ; s += 256)
            vpad_out[b * SQ + s] = (s >= nl) ? 1.0f : 0.0f;
    }
}

// ---------------------------------------------------------------------------
// Kernel C: scatter compacted rows, 4 rows per block (MLP 4).
// ---------------------------------------------------------------------------
__global__ __launch_bounds__(256, 4)
void scatter_kernel(const float* __restrict__ X, float* __restrict__ V)
{
    const int b = blockIdx.y;
    const int r0 = blockIdx.x * 4;
    const int tid = threadIdx.x;
    const int nl = g_newlen[b];

#pragma unroll
    for (int j = 0; j < 4; j++) {
        const int r = r0 + j;
        float4* vrow = (float4*)(V + ((size_t)b * SQ + r) * DD);
        if (r < nl) {
            const int s = g_idx[b][r];
            const float g = g_yfin[b * SQ + s];
            const float4* xrow = (const float4*)(X + ((size_t)b * SQ + s) * DD);
            float4 xv = xrow[tid];
            vrow[tid] = make_float4(xv.x * g, xv.y * g, xv.z * g, xv.w * g);
        } else {
            vrow[tid] = make_float4(0.0f, 0.0f, 0.0f, 0.0f);
        }
    }
}

// ---------------------------------------------------------------------------
extern "C" void kernel_launch(void* const* d_in, const int* in_sizes, int n_in,
                              void* d_out, int out_size)
{
    const float*        x   = (const float*)d_in[0];
    const unsigned int* pad = (const unsigned int*)d_in[1];
    const float*        W1  = (const float*)d_in[2];
    const float*        b1  = (const float*)d_in[3];
    const float*        W2  = (const float*)d_in[4];
    const float*        b2  = (const float*)d_in[5];
    float* out = (float*)d_out;

    const long v_elems = (long)MM * DD;
    int write_vpad = (out_size > v_elems) ? 1 : 0;
    float* vpad = out + v_elems;

    cudaFuncSetAttribute(gemm_hmma,
                         cudaFuncAttributeMaxDynamicSharedMemorySize, SM_TOT);

    pad_len_kernel<<<BQ, 256>>>(pad);
    xconv_kernel<<<MM, 256>>>(x);
    w1_split_kernel<<<dim3(DD / 32, DH / 32), dim3(32, 8)>>>(W1);
    gemm_hmma<<<dim3(NG, MM / TM), 256, SM_TOT>>>(b1, W2);
    zflag_kernel<<<MM / 256, 256>>>(b2);
    refine_kernel<<<128, 1024>>>(x, W1, b1, W2, b2);
    gate_select_kernel<<<BQ, 256>>>(vpad, write_vpad);
    scatter_kernel<<<dim3(SQ / 4, BQ), 256>>>(x, out);
}

// round 14
// speedup vs baseline: 2.1209x; 1.0252x over previous
#include <cuda_runtime.h>
#include <cuda_fp16.h>
#include <cstdint>

// Problem shape (fixed by setup_inputs)
#define BQ 8
#define SQ 4096
#define DD 1024
#define DH 512
#define MM (BQ * SQ)           // 32768 tokens

#define THRESHOLD 0.1f
#define EPSV 1e-05f
#define ZTHR (-0.10986122886681098f)   // atanh(2*0.1-1)/10
#define BAND 6e-3f
#define MAXFLAG 8192

// GEMM tiling
#define TM 128                 // tokens per CTA
#define TN 64                  // hidden units per CTA
#define BK 64                  // K per chunk
#define NCH (DD / BK)          // 16
#define NG (DH / TN)           // 8 N-groups

// smem: per stage = A(16KB) + B(8KB) = 24KB; 2 stages = 48KB.
#define SM_B1    0             // 64 floats
#define SM_W2    256
#define SM_RED   512           // float[128][2] = 1KB
#define SM_TILE  2048
#define STAGE_SZ 24576
#define SM_TOT   (SM_TILE + 2 * STAGE_SZ)   // 51200

// Device scratch
__device__ __half g_xh[MM * DD];       // X rounded to fp16 (64MB)
__device__ __half g_w1h[DH * DD];      // transposed W1 fp16 [n*DD + k]
__device__ float g_yp[NG][MM];         // per-N-group partial logits
__device__ float g_z[MM];              // full logits (incl b2)
__device__ float g_yfin[MM];           // final gate values
__device__ int   g_len[BQ];            // valid lengths per batch
__device__ int   g_idx[BQ][SQ];
__device__ int   g_newlen[BQ];
__device__ int   g_nflag;
__device__ int   g_flag[MAXFLAG];

// ---------------------------------------------------------------------------
__device__ __forceinline__ uint32_t smem_u32(const void* p) {
    uint32_t a;
    asm("{ .reg .u64 t; cvta.to.shared.u64 t, %1; cvt.u32.u64 %0, t; }"
        : "=r"(a) : "l"(p));
    return a;
}
__device__ __forceinline__ void ldm_x4(uint32_t& r0, uint32_t& r1,
                                       uint32_t& r2, uint32_t& r3, uint32_t addr) {
    asm volatile("ldmatrix.sync.aligned.m8n8.x4.shared.b16 {%0,%1,%2,%3}, [%4];"
                 : "=r"(r0), "=r"(r1), "=r"(r2), "=r"(r3) : "r"(addr));
}
__device__ __forceinline__ void mma_f16(float* d, const uint32_t* a,
                                        uint32_t b0, uint32_t b1) {
    asm volatile(
        "mma.sync.aligned.m16n8k16.row.col.f32.f16.f16.f32 "
        "{%0,%1,%2,%3}, {%4,%5,%6,%7}, {%8,%9}, {%0,%1,%2,%3};"
        : "+f"(d[0]), "+f"(d[1]), "+f"(d[2]), "+f"(d[3])
        : "r"(a[0]), "r"(a[1]), "r"(a[2]), "r"(a[3]), "r"(b0), "r"(b1));
}
__device__ __forceinline__ void cp16(uint32_t dst, const void* src) {
    asm volatile("cp.async.cg.shared.global [%0], [%1], 16;"
                 :: "r"(dst), "l"(src));
}
#define CP_COMMIT() asm volatile("cp.async.commit_group;" ::: "memory")
#define CP_WAIT1()  asm volatile("cp.async.wait_group 1;" ::: "memory")

// ---------------------------------------------------------------------------
// Kernel P: per-batch valid length from pad (4-byte elems, nonzero = padded).
// ---------------------------------------------------------------------------
__global__ __launch_bounds__(256, 4)
void pad_len_kernel(const unsigned int* __restrict__ pad)
{
    __shared__ int ired[256];
    const int b = blockIdx.x;
    const int tid = threadIdx.x;
    if (b == 0 && tid == 0) g_nflag = 0;
    int lc = 0;
    for (int s = tid; s < SQ; s += 256)
        lc += (pad[b * SQ + s] == 0u) ? 1 : 0;
    ired[tid] = lc;
    __syncthreads();
    for (int o = 128; o > 0; o >>= 1) {
        if (tid < o) ired[tid] += ired[tid + o];
        __syncthreads();
    }
    if (tid == 0) g_len[b] = ired[0];
}

// ---------------------------------------------------------------------------
// Kernel X: convert X fp32 -> fp16, one block per token; padded tokens skipped.
// ---------------------------------------------------------------------------
__global__ __launch_bounds__(256, 8)
void xconv_kernel(const float* __restrict__ X)
{
    const int t = blockIdx.x;
    const int s = t & (SQ - 1);
    if (s >= g_len[t >> 12]) return;
    const int i = t * 256 + threadIdx.x;   // per 4 elements
    const float4 v = ((const float4*)X)[i];
    __half2 h0 = __floats2half2_rn(v.x, v.y);
    __half2 h1 = __floats2half2_rn(v.z, v.w);
    uint2 o;
    o.x = *(uint32_t*)&h0;
    o.y = *(uint32_t*)&h1;
    ((uint2*)g_xh)[i] = o;
}

// ---------------------------------------------------------------------------
// Kernel 0: coalesced tiled transpose + fp16 round of W1.
// ---------------------------------------------------------------------------
__global__ __launch_bounds__(256, 6)
void w1_split_kernel(const float* __restrict__ W1) {
    __shared__ float tile[32][33];
    const int k0 = blockIdx.x * 32;
    const int n0 = blockIdx.y * 32;
    const int tx = threadIdx.x;   // 0..31
    const int ty = threadIdx.y;   // 0..7

#pragma unroll
    for (int j = 0; j < 4; j++) {
        const int k = k0 + ty + j * 8;
        tile[ty + j * 8][tx] = W1[(size_t)k * DH + n0 + tx];
    }
    __syncthreads();

#pragma unroll
    for (int j = 0; j < 4; j++) {
        const int n = n0 + ty + j * 8;
        g_w1h[(size_t)n * DD + k0 + tx] = __float2half_rn(tile[tx][ty + j * 8]);
    }
}

// ---------------------------------------------------------------------------
// Kernel A: pure fp16 HMMA GEMM, TM=128 x TN=64 tile, 2-stage cp.async,
// 4 CTAs/SM (8 warps/SMSP). Padded M-tiles skipped.
// ---------------------------------------------------------------------------
__global__ __launch_bounds__(256, 4)
void gemm_hmma(const float* __restrict__ b1,
               const float* __restrict__ W2)
{
    extern __shared__ char smem[];
    const uint32_t sbase = smem_u32(smem);
    const int tid = threadIdx.x;
    const int wid = tid >> 5;
    const int lane = tid & 31;
    const int wm = wid & 3;          // M quadrant (32 rows)
    const int wn = wid >> 2;         // N half (32 cols)
    const int n0 = blockIdx.x * TN;
    const int m0 = blockIdx.y * TM;

    // Early exit: tile fully in trailing padding -> logits never read.
    const int bq = m0 >> 12;
    const int s0 = m0 & (SQ - 1);
    if (s0 >= g_len[bq]) return;

    float* b1s = (float*)(smem + SM_B1);
    float* w2s = (float*)(smem + SM_W2);
    float (*red)[2] = (float(*)[2])(smem + SM_RED);
    if (tid < TN) {
        b1s[tid] = b1[n0 + tid];
        w2s[tid] = W2[n0 + tid];
    }

    float acc[2][4][4];
#pragma unroll
    for (int mt = 0; mt < 2; mt++)
#pragma unroll
        for (int nt = 0; nt < 4; nt++)
#pragma unroll
            for (int e = 0; e < 4; e++) acc[mt][nt][e] = 0.0f;

    // A cp mapping: 2 threads per row (halves of 64-K)
    const int arow = tid >> 1;
    const int ahalf = tid & 1;
    const int arx = arow & 7;
    const uint32_t arb = (uint32_t)arow * 128u;
    // B cp mapping: 4 threads per row (quarters)
    const int brow = tid >> 2;
    const int bq4 = tid & 3;
    const int brx = brow & 7;
    const uint32_t brb = (uint32_t)brow * 128u;

    const __half* Ap = g_xh + (size_t)(m0 + arow) * DD + ahalf * 32;
    const __half* Bp = g_w1h + (size_t)(n0 + brow) * DD + bq4 * 16;

#define CP_CHUNK(c, st) do {                                                \
    const int _k0 = (c) * BK;                                               \
    const uint32_t _sa = sbase + SM_TILE + (st) * STAGE_SZ;                 \
    _Pragma("unroll")                                                       \
    for (int j = 0; j < 4; j++) {                                           \
        const uint32_t _co = (uint32_t)(((ahalf * 4 + j) ^ arx) * 16);      \
        cp16(_sa + arb + _co, Ap + _k0 + j * 8);                            \
    }                                                                       \
    _Pragma("unroll")                                                       \
    for (int j = 0; j < 2; j++) {                                           \
        const uint32_t _co = (uint32_t)(((bq4 * 2 + j) ^ brx) * 16);        \
        cp16(_sa + 16384 + brb + _co, Bp + _k0 + j * 8);                    \
    }                                                                       \
} while (0)

    // Prologue: fill both stages
    CP_CHUNK(0, 0);
    CP_COMMIT();
    CP_CHUNK(1, 1);
    CP_COMMIT();

    for (int c = 0; c < NCH; c++) {
        const int st = c & 1;
        CP_WAIT1();
        __syncthreads();

        const uint32_t abase = sbase + SM_TILE + st * STAGE_SZ;
#pragma unroll
        for (int ks = 0; ks < 4; ks++) {
            uint32_t a[2][4];        // [mtile][4]
            uint32_t bb[2][4];       // [npair][4]
            const int cc = ks * 2 + (lane >> 4);
#pragma unroll
            for (int mt = 0; mt < 2; mt++) {
                const int r = wm * 32 + mt * 16 + (lane & 15);
                const uint32_t addr = abase + r * 128 + ((cc ^ (r & 7)) * 16);
                ldm_x4(a[mt][0], a[mt][1], a[mt][2], a[mt][3], addr);
            }
#pragma unroll
            for (int np = 0; np < 2; np++) {
                const int r = wn * 32 + np * 16 + (lane & 15);
                const uint32_t addr = abase + 16384
                                    + r * 128 + ((cc ^ (r & 7)) * 16);
                ldm_x4(bb[np][0], bb[np][1], bb[np][2], bb[np][3], addr);
            }
#pragma unroll
            for (int mt = 0; mt < 2; mt++)
#pragma unroll
                for (int nt = 0; nt < 4; nt++) {
                    const int np = nt >> 1, sel = nt & 1;
                    mma_f16(acc[mt][nt], a[mt], bb[np][sel], bb[np][sel + 2]);
                }
        }
        __syncthreads();
        if (c + 2 < NCH) {
            CP_CHUNK(c + 2, st);
            CP_COMMIT();
        } else {
            CP_COMMIT();
        }
    }

    // Epilogue: p = sum_cols relu(acc + b1) * w2, reduce across quads + wn.
#pragma unroll
    for (int mt = 0; mt < 2; mt++) {
        float p0 = 0.0f, p1 = 0.0f;
#pragma unroll
        for (int nt = 0; nt < 4; nt++) {
            const int cl = wn * 32 + nt * 8 + (lane & 3) * 2;
            const float w0 = w2s[cl], w1v = w2s[cl + 1];
            const float c0 = b1s[cl], c1 = b1s[cl + 1];
            p0 = fmaf(fmaxf(acc[mt][nt][0] + c0, 0.0f), w0, p0);
            p0 = fmaf(fmaxf(acc[mt][nt][1] + c1, 0.0f), w1v, p0);
            p1 = fmaf(fmaxf(acc[mt][nt][2] + c0, 0.0f), w0, p1);
            p1 = fmaf(fmaxf(acc[mt][nt][3] + c1, 0.0f), w1v, p1);
        }
        p0 += __shfl_xor_sync(0xffffffffu, p0, 1);
        p0 += __shfl_xor_sync(0xffffffffu, p0, 2);
        p1 += __shfl_xor_sync(0xffffffffu, p1, 1);
        p1 += __shfl_xor_sync(0xffffffffu, p1, 2);
        if ((lane & 3) == 0) {
            const int r0 = wm * 32 + mt * 16 + (lane >> 2);
            red[r0][wn] = p0;
            red[r0 + 8][wn] = p1;
        }
    }
    __syncthreads();
    if (tid < TM)
        g_yp[blockIdx.x][m0 + tid] = red[tid][0] + red[tid][1];
}

// ---------------------------------------------------------------------------
// Kernel B1: sum partials -> z, flag tokens within BAND of threshold.
// ---------------------------------------------------------------------------
__global__ __launch_bounds__(256, 8)
void zflag_kernel(const float* __restrict__ b2)
{
    const int t = blockIdx.x * 256 + threadIdx.x;
    const int b = t >> 12;
    const int s = t & (SQ - 1);
    if (s >= g_len[b]) { g_z[t] = 0.0f; return; }
    float z = b2[0];
#pragma unroll
    for (int g = 0; g < NG; g++) z += g_yp[g][t];
    g_z[t] = z;
    if (fabsf(z - ZTHR) < BAND) {
        int i = atomicAdd(&g_nflag, 1);
        if (i < MAXFLAG) g_flag[i] = t;
    }
}

// ---------------------------------------------------------------------------
// Kernel R: exact fp32 recompute of flagged tokens' logits.
// One block (1024 thr) per flagged token: 8 k-groups x 128 h-quads.
// ---------------------------------------------------------------------------
__global__ __launch_bounds__(1024, 1)
void refine_kernel(const float* __restrict__ X,
                   const float* __restrict__ W1,
                   const float* __restrict__ b1,
                   const float* __restrict__ W2,
                   const float* __restrict__ b2)
{
    __shared__ float  xs[DD];           // 4KB
    __shared__ float4 part[8][128];     // 16KB
    __shared__ float  rr[4];
    const int tid = threadIdx.x;
    const int kg = tid >> 7;            // 0..7
    const int hq = tid & 127;           // h quad: h = hq*4..hq*4+3
    int n = g_nflag;
    if (n > MAXFLAG) n = MAXFLAG;

    for (int i = blockIdx.x; i < n; i += gridDim.x) {
        const int t = g_flag[i];
        if (tid < DD) xs[tid] = X[(size_t)t * DD + tid];
        __syncthreads();

        const float4* Wp = (const float4*)W1 + hq;
        float4 acc = make_float4(0.0f, 0.0f, 0.0f, 0.0f);
        const int k0 = kg * 128;
#pragma unroll 8
        for (int k = k0; k < k0 + 128; k++) {
            const float xk = xs[k];
            const float4 w = Wp[(size_t)k * (DH / 4)];
            acc.x = fmaf(xk, w.x, acc.x);
            acc.y = fmaf(xk, w.y, acc.y);
            acc.z = fmaf(xk, w.z, acc.z);
            acc.w = fmaf(xk, w.w, acc.w);
        }
        part[kg][hq] = acc;
        __syncthreads();

        if (tid < 128) {
            float4 s = part[0][tid];
#pragma unroll
            for (int g = 1; g < 8; g++) {
                const float4 q = part[g][tid];
                s.x += q.x; s.y += q.y; s.z += q.z; s.w += q.w;
            }
            const float4 bb = ((const float4*)b1)[tid];
            const float4 ww = ((const float4*)W2)[tid];
            float p;
            p  = fmaxf(s.x + bb.x, 0.0f) * ww.x;
            p += fmaxf(s.y + bb.y, 0.0f) * ww.y;
            p += fmaxf(s.z + bb.z, 0.0f) * ww.z;
            p += fmaxf(s.w + bb.w, 0.0f) * ww.w;
            p += __shfl_xor_sync(0xffffffffu, p, 16);
            p += __shfl_xor_sync(0xffffffffu, p, 8);
            p += __shfl_xor_sync(0xffffffffu, p, 4);
            p += __shfl_xor_sync(0xffffffffu, p, 2);
            p += __shfl_xor_sync(0xffffffffu, p, 1);
            if ((tid & 31) == 0) rr[tid >> 5] = p;
        }
        __syncthreads();
        if (tid == 0) g_z[t] = rr[0] + rr[1] + rr[2] + rr[3] + b2[0];
        __syncthreads();
    }
}

// ---------------------------------------------------------------------------
// Kernel B2: per-batch squash, max/adjust, compaction. Uses g_len.
// ---------------------------------------------------------------------------
__global__ __launch_bounds__(256, 1)
void gate_select_kernel(float* __restrict__ vpad_out, int write_vpad)
{
    const int b = blockIdx.x;
    const int tid = threadIdx.x;

    __shared__ float ysm[SQ];
    __shared__ float fred[256];
    __shared__ int   cnt[256];

    const int length = g_len[b];

    float mx = 0.0f;
    for (int s = tid; s < SQ; s += 256) {
        float y = (s < length)
                ? (1.0f + tanhf(10.0f * g_z[b * SQ + s])) * 0.5f : 0.0f;
        ysm[s] = y;
        mx = fmaxf(mx, y);
    }
    fred[tid] = mx;
    __syncthreads();
    for (int o = 128; o > 0; o >>= 1) {
        if (tid < o) fred[tid] = fmaxf(fred[tid], fred[tid + o]);
        __syncthreads();
    }
    const float adjust = fmaxf(0.0f, EPSV + THRESHOLD - fred[0]);
    __syncthreads();

    for (int s = tid; s < SQ; s += 256) {
        float yf = ysm[s] + adjust;
        ysm[s] = yf;
        g_yfin[b * SQ + s] = yf;
    }
    __syncthreads();

    const int CH = SQ / 256;
    const int base = tid * CH;
    int c = 0;
#pragma unroll
    for (int i = 0; i < CH; i++) {
        int s = base + i;
        c += (ysm[s] > THRESHOLD && s < length) ? 1 : 0;
    }
    cnt[tid] = c;
    __syncthreads();
    for (int o = 1; o < 256; o <<= 1) {
        int v = (tid >= o) ? cnt[tid - o] : 0;
        __syncthreads();
        cnt[tid] += v;
        __syncthreads();
    }
    int off = cnt[tid] - c;
#pragma unroll
    for (int i = 0; i < CH; i++) {
        int s = base + i;
        if (ysm[s] > THRESHOLD && s < length) g_idx[b][off++] = s;
    }
    const int nl = cnt[255];
    if (tid == 0) g_newlen[b] = nl;

    if (write_vpad) {
        for (int s = tid; s < SQ; s += 256)
            vpad_out[b * SQ + s] = (s >= nl) ? 1.0f : 0.0f;
    }
}

// ---------------------------------------------------------------------------
// Kernel C: scatter compacted rows, 4 rows per block (MLP 4).
// ---------------------------------------------------------------------------
__global__ __launch_bounds__(256, 4)
void scatter_kernel(const float* __restrict__ X, float* __restrict__ V)
{
    const int b = blockIdx.y;
    const int r0 = blockIdx.x * 4;
    const int tid = threadIdx.x;
    const int nl = g_newlen[b];

#pragma unroll
    for (int j = 0; j < 4; j++) {
        const int r = r0 + j;
        float4* vrow = (float4*)(V + ((size_t)b * SQ + r) * DD);
        if (r < nl) {
            const int s = g_idx[b][r];
            const float g = g_yfin[b * SQ + s];
            const float4* xrow = (const float4*)(X + ((size_t)b * SQ + s) * DD);
            float4 xv = xrow[tid];
            vrow[tid] = make_float4(xv.x * g, xv.y * g, xv.z * g, xv.w * g);
        } else {
            vrow[tid] = make_float4(0.0f, 0.0f, 0.0f, 0.0f);
        }
    }
}

// ---------------------------------------------------------------------------
extern "C" void kernel_launch(void* const* d_in, const int* in_sizes, int n_in,
                              void* d_out, int out_size)
{
    const float*        x   = (const float*)d_in[0];
    const unsigned int* pad = (const unsigned int*)d_in[1];
    const float*        W1  = (const float*)d_in[2];
    const float*        b1  = (const float*)d_in[3];
    const float*        W2  = (const float*)d_in[4];
    const float*        b2  = (const float*)d_in[5];
    float* out = (float*)d_out;

    const long v_elems = (long)MM * DD;
    int write_vpad = (out_size > v_elems) ? 1 : 0;
    float* vpad = out + v_elems;

    cudaFuncSetAttribute(gemm_hmma,
                         cudaFuncAttributeMaxDynamicSharedMemorySize, SM_TOT);

    pad_len_kernel<<<BQ, 256>>>(pad);
    xconv_kernel<<<MM, 256>>>(x);
    w1_split_kernel<<<dim3(DD / 32, DH / 32), dim3(32, 8)>>>(W1);
    gemm_hmma<<<dim3(NG, MM / TM), 256, SM_TOT>>>(b1, W2);
    zflag_kernel<<<MM / 256, 256>>>(b2);
    refine_kernel<<<128, 1024>>>(x, W1, b1, W2, b2);
    gate_select_kernel<<<BQ, 256>>>(vpad, write_vpad);
    scatter_kernel<<<dim3(SQ / 4, BQ), 256>>>(x, out);
}

// round 15
// speedup vs baseline: 2.1660x; 1.0213x over previous
#include <cuda_runtime.h>
#include <cuda_fp16.h>
#include <cstdint>

// Problem shape (fixed by setup_inputs)
#define BQ 8
#define SQ 4096
#define DD 1024
#define DH 512
#define MM (BQ * SQ)           // 32768 tokens

#define THRESHOLD 0.1f
#define EPSV 1e-05f
#define ZTHR (-0.10986122886681098f)   // atanh(2*0.1-1)/10
#define BAND 6e-3f
#define MAXFLAG 8192

// GEMM tiling
#define TM 128                 // tokens per CTA
#define TN 64                  // hidden units per CTA
#define BK 64                  // K per chunk
#define NCH (DD / BK)          // 16
#define NG (DH / TN)           // 8 N-groups

// smem: per stage = A(16KB) + B(8KB) = 24KB; 2 stages = 48KB.
#define SM_B1    0             // 64 floats
#define SM_W2    256
#define SM_RED   512           // float[128][2] = 1KB
#define SM_TILE  2048
#define STAGE_SZ 24576
#define SM_TOT   (SM_TILE + 2 * STAGE_SZ)   // 51200

// Device scratch
__device__ __half g_xh[MM * DD];       // X rounded to fp16 (64MB)
__device__ __half g_w1h[DH * DD];      // transposed W1 fp16 [n*DD + k]
__device__ float g_yp[NG][MM];         // per-N-group partial logits
__device__ float g_z[MM];              // full logits (incl b2)
__device__ float g_yfin[MM];           // final gate values
__device__ int   g_len[BQ];            // valid lengths per batch
__device__ int   g_idx[BQ][SQ];
__device__ int   g_newlen[BQ];
__device__ int   g_nflag;
__device__ int   g_flag[MAXFLAG];

// ---------------------------------------------------------------------------
__device__ __forceinline__ uint32_t smem_u32(const void* p) {
    uint32_t a;
    asm("{ .reg .u64 t; cvta.to.shared.u64 t, %1; cvt.u32.u64 %0, t; }"
        : "=r"(a) : "l"(p));
    return a;
}
__device__ __forceinline__ void ldm_x4(uint32_t& r0, uint32_t& r1,
                                       uint32_t& r2, uint32_t& r3, uint32_t addr) {
    asm volatile("ldmatrix.sync.aligned.m8n8.x4.shared.b16 {%0,%1,%2,%3}, [%4];"
                 : "=r"(r0), "=r"(r1), "=r"(r2), "=r"(r3) : "r"(addr));
}
__device__ __forceinline__ void mma_f16(float* d, const uint32_t* a,
                                        uint32_t b0, uint32_t b1) {
    asm volatile(
        "mma.sync.aligned.m16n8k16.row.col.f32.f16.f16.f32 "
        "{%0,%1,%2,%3}, {%4,%5,%6,%7}, {%8,%9}, {%0,%1,%2,%3};"
        : "+f"(d[0]), "+f"(d[1]), "+f"(d[2]), "+f"(d[3])
        : "r"(a[0]), "r"(a[1]), "r"(a[2]), "r"(a[3]), "r"(b0), "r"(b1));
}
__device__ __forceinline__ void cp16(uint32_t dst, const void* src) {
    asm volatile("cp.async.cg.shared.global [%0], [%1], 16;"
                 :: "r"(dst), "l"(src));
}
#define CP_COMMIT() asm volatile("cp.async.commit_group;" ::: "memory")
#define CP_WAIT1()  asm volatile("cp.async.wait_group 1;" ::: "memory")

// ---------------------------------------------------------------------------
// Kernel P: fused prep. Blocks 0..7: per-batch valid length from pad.
// Blocks 8..519: tiled transpose + fp16 round of W1 (32x32 tiles).
// ---------------------------------------------------------------------------
__global__ __launch_bounds__(256, 4)
void prep_kernel(const unsigned int* __restrict__ pad,
                 const float* __restrict__ W1)
{
    const int tid = threadIdx.x;
    if (blockIdx.x < BQ) {
        __shared__ int ired[256];
        const int b = blockIdx.x;
        if (b == 0 && tid == 0) g_nflag = 0;
        int lc = 0;
        for (int s = tid; s < SQ; s += 256)
            lc += (pad[b * SQ + s] == 0u) ? 1 : 0;
        ired[tid] = lc;
        __syncthreads();
        for (int o = 128; o > 0; o >>= 1) {
            if (tid < o) ired[tid] += ired[tid + o];
            __syncthreads();
        }
        if (tid == 0) g_len[b] = ired[0];
    } else {
        __shared__ float tile[32][33];
        const int idx = blockIdx.x - BQ;          // 0..511
        const int k0 = (idx & 31) * 32;           // 32 k-tiles
        const int n0 = (idx >> 5) * 32;           // 16 n-tiles
        const int tx = tid & 31;
        const int ty = tid >> 5;

#pragma unroll
        for (int j = 0; j < 4; j++) {
            const int k = k0 + ty + j * 8;
            tile[ty + j * 8][tx] = W1[(size_t)k * DH + n0 + tx];
        }
        __syncthreads();

#pragma unroll
        for (int j = 0; j < 4; j++) {
            const int n = n0 + ty + j * 8;
            g_w1h[(size_t)n * DD + k0 + tx] =
                __float2half_rn(tile[tx][ty + j * 8]);
        }
    }
}

// ---------------------------------------------------------------------------
// Kernel X: convert X fp32 -> fp16, one block per token; padded tokens skipped.
// ---------------------------------------------------------------------------
__global__ __launch_bounds__(256, 8)
void xconv_kernel(const float* __restrict__ X)
{
    const int t = blockIdx.x;
    const int s = t & (SQ - 1);
    if (s >= g_len[t >> 12]) return;
    const int i = t * 256 + threadIdx.x;   // per 4 elements
    const float4 v = ((const float4*)X)[i];
    __half2 h0 = __floats2half2_rn(v.x, v.y);
    __half2 h1 = __floats2half2_rn(v.z, v.w);
    uint2 o;
    o.x = *(uint32_t*)&h0;
    o.y = *(uint32_t*)&h1;
    ((uint2*)g_xh)[i] = o;
}

// ---------------------------------------------------------------------------
// Kernel A: pure fp16 HMMA GEMM, TM=128 x TN=64 tile, 2-stage cp.async,
// 4 CTAs/SM (8 warps/SMSP). Padded M-tiles skipped.
// ---------------------------------------------------------------------------
__global__ __launch_bounds__(256, 4)
void gemm_hmma(const float* __restrict__ b1,
               const float* __restrict__ W2)
{
    extern __shared__ char smem[];
    const uint32_t sbase = smem_u32(smem);
    const int tid = threadIdx.x;
    const int wid = tid >> 5;
    const int lane = tid & 31;
    const int wm = wid & 3;          // M quadrant (32 rows)
    const int wn = wid >> 2;         // N half (32 cols)
    const int n0 = blockIdx.x * TN;
    const int m0 = blockIdx.y * TM;

    // Early exit: tile fully in trailing padding -> logits never read.
    const int bq = m0 >> 12;
    const int s0 = m0 & (SQ - 1);
    if (s0 >= g_len[bq]) return;

    float* b1s = (float*)(smem + SM_B1);
    float* w2s = (float*)(smem + SM_W2);
    float (*red)[2] = (float(*)[2])(smem + SM_RED);
    if (tid < TN) {
        b1s[tid] = b1[n0 + tid];
        w2s[tid] = W2[n0 + tid];
    }

    float acc[2][4][4];
#pragma unroll
    for (int mt = 0; mt < 2; mt++)
#pragma unroll
        for (int nt = 0; nt < 4; nt++)
#pragma unroll
            for (int e = 0; e < 4; e++) acc[mt][nt][e] = 0.0f;

    // A cp mapping: 2 threads per row (halves of 64-K)
    const int arow = tid >> 1;
    const int ahalf = tid & 1;
    const int arx = arow & 7;
    const uint32_t arb = (uint32_t)arow * 128u;
    // B cp mapping: 4 threads per row (quarters)
    const int brow = tid >> 2;
    const int bq4 = tid & 3;
    const int brx = brow & 7;
    const uint32_t brb = (uint32_t)brow * 128u;

    const __half* Ap = g_xh + (size_t)(m0 + arow) * DD + ahalf * 32;
    const __half* Bp = g_w1h + (size_t)(n0 + brow) * DD + bq4 * 16;

#define CP_CHUNK(c, st) do {                                                \
    const int _k0 = (c) * BK;                                               \
    const uint32_t _sa = sbase + SM_TILE + (st) * STAGE_SZ;                 \
    _Pragma("unroll")                                                       \
    for (int j = 0; j < 4; j++) {                                           \
        const uint32_t _co = (uint32_t)(((ahalf * 4 + j) ^ arx) * 16);      \
        cp16(_sa + arb + _co, Ap + _k0 + j * 8);                            \
    }                                                                       \
    _Pragma("unroll")                                                       \
    for (int j = 0; j < 2; j++) {                                           \
        const uint32_t _co = (uint32_t)(((bq4 * 2 + j) ^ brx) * 16);        \
        cp16(_sa + 16384 + brb + _co, Bp + _k0 + j * 8);                    \
    }                                                                       \
} while (0)

    // Prologue: fill both stages
    CP_CHUNK(0, 0);
    CP_COMMIT();
    CP_CHUNK(1, 1);
    CP_COMMIT();

    for (int c = 0; c < NCH; c++) {
        const int st = c & 1;
        CP_WAIT1();
        __syncthreads();

        const uint32_t abase = sbase + SM_TILE + st * STAGE_SZ;
#pragma unroll
        for (int ks = 0; ks < 4; ks++) {
            uint32_t a[2][4];        // [mtile][4]
            uint32_t bb[2][4];       // [npair][4]
            const int cc = ks * 2 + (lane >> 4);
#pragma unroll
            for (int mt = 0; mt < 2; mt++) {
                const int r = wm * 32 + mt * 16 + (lane & 15);
                const uint32_t addr = abase + r * 128 + ((cc ^ (r & 7)) * 16);
                ldm_x4(a[mt][0], a[mt][1], a[mt][2], a[mt][3], addr);
            }
#pragma unroll
            for (int np = 0; np < 2; np++) {
                const int r = wn * 32 + np * 16 + (lane & 15);
                const uint32_t addr = abase + 16384
                                    + r * 128 + ((cc ^ (r & 7)) * 16);
                ldm_x4(bb[np][0], bb[np][1], bb[np][2], bb[np][3], addr);
            }
#pragma unroll
            for (int mt = 0; mt < 2; mt++)
#pragma unroll
                for (int nt = 0; nt < 4; nt++) {
                    const int np = nt >> 1, sel = nt & 1;
                    mma_f16(acc[mt][nt], a[mt], bb[np][sel], bb[np][sel + 2]);
                }
        }
        __syncthreads();
        if (c + 2 < NCH) {
            CP_CHUNK(c + 2, st);
            CP_COMMIT();
        } else {
            CP_COMMIT();
        }
    }

    // Epilogue: p = sum_cols relu(acc + b1) * w2, reduce across quads + wn.
#pragma unroll
    for (int mt = 0; mt < 2; mt++) {
        float p0 = 0.0f, p1 = 0.0f;
#pragma unroll
        for (int nt = 0; nt < 4; nt++) {
            const int cl = wn * 32 + nt * 8 + (lane & 3) * 2;
            const float w0 = w2s[cl], w1v = w2s[cl + 1];
            const float c0 = b1s[cl], c1 = b1s[cl + 1];
            p0 = fmaf(fmaxf(acc[mt][nt][0] + c0, 0.0f), w0, p0);
            p0 = fmaf(fmaxf(acc[mt][nt][1] + c1, 0.0f), w1v, p0);
            p1 = fmaf(fmaxf(acc[mt][nt][2] + c0, 0.0f), w0, p1);
            p1 = fmaf(fmaxf(acc[mt][nt][3] + c1, 0.0f), w1v, p1);
        }
        p0 += __shfl_xor_sync(0xffffffffu, p0, 1);
        p0 += __shfl_xor_sync(0xffffffffu, p0, 2);
        p1 += __shfl_xor_sync(0xffffffffu, p1, 1);
        p1 += __shfl_xor_sync(0xffffffffu, p1, 2);
        if ((lane & 3) == 0) {
            const int r0 = wm * 32 + mt * 16 + (lane >> 2);
            red[r0][wn] = p0;
            red[r0 + 8][wn] = p1;
        }
    }
    __syncthreads();
    if (tid < TM)
        g_yp[blockIdx.x][m0 + tid] = red[tid][0] + red[tid][1];
}

// ---------------------------------------------------------------------------
// Kernel B1: sum partials -> z, flag tokens within BAND of threshold.
// ---------------------------------------------------------------------------
__global__ __launch_bounds__(256, 8)
void zflag_kernel(const float* __restrict__ b2)
{
    const int t = blockIdx.x * 256 + threadIdx.x;
    const int b = t >> 12;
    const int s = t & (SQ - 1);
    if (s >= g_len[b]) { g_z[t] = 0.0f; return; }
    float z = b2[0];
#pragma unroll
    for (int g = 0; g < NG; g++) z += g_yp[g][t];
    g_z[t] = z;
    if (fabsf(z - ZTHR) < BAND) {
        int i = atomicAdd(&g_nflag, 1);
        if (i < MAXFLAG) g_flag[i] = t;
    }
}

// ---------------------------------------------------------------------------
// Kernel R: exact fp32 recompute of flagged tokens' logits.
// One block (1024 thr) per flagged token: 8 k-groups x 128 h-quads.
// ---------------------------------------------------------------------------
__global__ __launch_bounds__(1024, 1)
void refine_kernel(const float* __restrict__ X,
                   const float* __restrict__ W1,
                   const float* __restrict__ b1,
                   const float* __restrict__ W2,
                   const float* __restrict__ b2)
{
    __shared__ float  xs[DD];           // 4KB
    __shared__ float4 part[8][128];     // 16KB
    __shared__ float  rr[4];
    const int tid = threadIdx.x;
    const int kg = tid >> 7;            // 0..7
    const int hq = tid & 127;           // h quad: h = hq*4..hq*4+3
    int n = g_nflag;
    if (n > MAXFLAG) n = MAXFLAG;

    for (int i = blockIdx.x; i < n; i += gridDim.x) {
        const int t = g_flag[i];
        if (tid < DD) xs[tid] = X[(size_t)t * DD + tid];
        __syncthreads();

        const float4* Wp = (const float4*)W1 + hq;
        float4 acc = make_float4(0.0f, 0.0f, 0.0f, 0.0f);
        const int k0 = kg * 128;
#pragma unroll 8
        for (int k = k0; k < k0 + 128; k++) {
            const float xk = xs[k];
            const float4 w = Wp[(size_t)k * (DH / 4)];
            acc.x = fmaf(xk, w.x, acc.x);
            acc.y = fmaf(xk, w.y, acc.y);
            acc.z = fmaf(xk, w.z, acc.z);
            acc.w = fmaf(xk, w.w, acc.w);
        }
        part[kg][hq] = acc;
        __syncthreads();

        if (tid < 128) {
            float4 s = part[0][tid];
#pragma unroll
            for (int g = 1; g < 8; g++) {
                const float4 q = part[g][tid];
                s.x += q.x; s.y += q.y; s.z += q.z; s.w += q.w;
            }
            const float4 bb = ((const float4*)b1)[tid];
            const float4 ww = ((const float4*)W2)[tid];
            float p;
            p  = fmaxf(s.x + bb.x, 0.0f) * ww.x;
            p += fmaxf(s.y + bb.y, 0.0f) * ww.y;
            p += fmaxf(s.z + bb.z, 0.0f) * ww.z;
            p += fmaxf(s.w + bb.w, 0.0f) * ww.w;
            p += __shfl_xor_sync(0xffffffffu, p, 16);
            p += __shfl_xor_sync(0xffffffffu, p, 8);
            p += __shfl_xor_sync(0xffffffffu, p, 4);
            p += __shfl_xor_sync(0xffffffffu, p, 2);
            p += __shfl_xor_sync(0xffffffffu, p, 1);
            if ((tid & 31) == 0) rr[tid >> 5] = p;
        }
        __syncthreads();
        if (tid == 0) g_z[t] = rr[0] + rr[1] + rr[2] + rr[3] + b2[0];
        __syncthreads();
    }
}

// ---------------------------------------------------------------------------
// Kernel B2: per-batch squash, max/adjust, compaction. 1024 threads.
// ---------------------------------------------------------------------------
__global__ __launch_bounds__(1024, 1)
void gate_select_kernel(float* __restrict__ vpad_out, int write_vpad)
{
    const int b = blockIdx.x;
    const int tid = threadIdx.x;

    __shared__ float ysm[SQ];
    __shared__ float fred[1024];
    __shared__ int   cnt[1024];

    const int length = g_len[b];

    float mx = 0.0f;
    for (int s = tid; s < SQ; s += 1024) {
        float y = (s < length)
                ? (1.0f + tanhf(10.0f * g_z[b * SQ + s])) * 0.5f : 0.0f;
        ysm[s] = y;
        mx = fmaxf(mx, y);
    }
    fred[tid] = mx;
    __syncthreads();
    for (int o = 512; o > 0; o >>= 1) {
        if (tid < o) fred[tid] = fmaxf(fred[tid], fred[tid + o]);
        __syncthreads();
    }
    const float adjust = fmaxf(0.0f, EPSV + THRESHOLD - fred[0]);
    __syncthreads();

    for (int s = tid; s < SQ; s += 1024) {
        float yf = ysm[s] + adjust;
        ysm[s] = yf;
        g_yfin[b * SQ + s] = yf;
    }
    __syncthreads();

    const int CH = SQ / 1024;     // 4 contiguous positions per thread
    const int base = tid * CH;
    int c = 0;
#pragma unroll
    for (int i = 0; i < CH; i++) {
        int s = base + i;
        c += (ysm[s] > THRESHOLD && s < length) ? 1 : 0;
    }
    cnt[tid] = c;
    __syncthreads();
    for (int o = 1; o < 1024; o <<= 1) {
        int v = (tid >= o) ? cnt[tid - o] : 0;
        __syncthreads();
        cnt[tid] += v;
        __syncthreads();
    }
    int off = cnt[tid] - c;
#pragma unroll
    for (int i = 0; i < CH; i++) {
        int s = base + i;
        if (ysm[s] > THRESHOLD && s < length) g_idx[b][off++] = s;
    }
    const int nl = cnt[1023];
    if (tid == 0) g_newlen[b] = nl;

    if (write_vpad) {
        for (int s = tid; s < SQ; s += 1024)
            vpad_out[b * SQ + s] = (s >= nl) ? 1.0f : 0.0f;
    }
}

// ---------------------------------------------------------------------------
// Kernel C: scatter compacted rows, 4 rows per block (MLP 4).
// ---------------------------------------------------------------------------
__global__ __launch_bounds__(256, 4)
void scatter_kernel(const float* __restrict__ X, float* __restrict__ V)
{
    const int b = blockIdx.y;
    const int r0 = blockIdx.x * 4;
    const int tid = threadIdx.x;
    const int nl = g_newlen[b];

#pragma unroll
    for (int j = 0; j < 4; j++) {
        const int r = r0 + j;
        float4* vrow = (float4*)(V + ((size_t)b * SQ + r) * DD);
        if (r < nl) {
            const int s = g_idx[b][r];
            const float g = g_yfin[b * SQ + s];
            const float4* xrow = (const float4*)(X + ((size_t)b * SQ + s) * DD);
            float4 xv = xrow[tid];
            vrow[tid] = make_float4(xv.x * g, xv.y * g, xv.z * g, xv.w * g);
        } else {
            vrow[tid] = make_float4(0.0f, 0.0f, 0.0f, 0.0f);
        }
    }
}

// ---------------------------------------------------------------------------
extern "C" void kernel_launch(void* const* d_in, const int* in_sizes, int n_in,
                              void* d_out, int out_size)
{
    const float*        x   = (const float*)d_in[0];
    const unsigned int* pad = (const unsigned int*)d_in[1];
    const float*        W1  = (const float*)d_in[2];
    const float*        b1  = (const float*)d_in[3];
    const float*        W2  = (const float*)d_in[4];
    const float*        b2  = (const float*)d_in[5];
    float* out = (float*)d_out;

    const long v_elems = (long)MM * DD;
    int write_vpad = (out_size > v_elems) ? 1 : 0;
    float* vpad = out + v_elems;

    cudaFuncSetAttribute(gemm_hmma,
                         cudaFuncAttributeMaxDynamicSharedMemorySize, SM_TOT);

    prep_kernel<<<BQ + 512, 256>>>(pad, W1);
    xconv_kernel<<<MM, 256>>>(x);
    gemm_hmma<<<dim3(NG, MM / TM), 256, SM_TOT>>>(b1, W2);
    zflag_kernel<<<MM / 256, 256>>>(b2);
    refine_kernel<<<128, 1024>>>(x, W1, b1, W2, b2);
    gate_select_kernel<<<BQ, 1024>>>(vpad, write_vpad);
    scatter_kernel<<<dim3(SQ / 4, BQ), 256>>>(x, out);
}

// round 16
// speedup vs baseline: 2.1931x; 1.0125x over previous
#include <cuda_runtime.h>
#include <cuda_fp16.h>
#include <cstdint>

// Problem shape (fixed by setup_inputs)
#define BQ 8
#define SQ 4096
#define DD 1024
#define DH 512
#define MM (BQ * SQ)           // 32768 tokens

#define THRESHOLD 0.1f
#define EPSV 1e-05f
#define ZTHR (-0.10986122886681098f)   // atanh(2*0.1-1)/10
#define BAND 6e-3f
#define MAXFLAG 8192

// GEMM tiling
#define TM 128                 // tokens per CTA
#define TN 64                  // hidden units per CTA
#define BK 64                  // K per chunk
#define NCH (DD / BK)          // 16
#define NG (DH / TN)           // 8 N-groups

// smem: per stage = A(16KB) + B(8KB) = 24KB; 2 stages = 48KB.
#define SM_B1    0             // 64 floats
#define SM_W2    256
#define SM_RED   512           // float[128][2] = 1KB
#define SM_TILE  2048
#define STAGE_SZ 24576
#define SM_TOT   (SM_TILE + 2 * STAGE_SZ)   // 51200

// Device scratch
__device__ __half g_xh[MM * DD];       // X rounded to fp16 (64MB)
__device__ __half g_w1h[DH * DD];      // transposed W1 fp16 [n*DD + k]
__device__ float g_yp[NG][MM];         // per-N-group partial logits
__device__ float g_z[MM];              // full logits (incl b2)
__device__ float g_yfin[MM];           // final gate values
__device__ int   g_len[BQ];            // valid lengths per batch
__device__ int   g_idx[BQ][SQ];
__device__ int   g_newlen[BQ];
__device__ int   g_nflag;
__device__ int   g_flag[MAXFLAG];

// ---------------------------------------------------------------------------
__device__ __forceinline__ uint32_t smem_u32(const void* p) {
    uint32_t a;
    asm("{ .reg .u64 t; cvta.to.shared.u64 t, %1; cvt.u32.u64 %0, t; }"
        : "=r"(a) : "l"(p));
    return a;
}
__device__ __forceinline__ void ldm_x4(uint32_t& r0, uint32_t& r1,
                                       uint32_t& r2, uint32_t& r3, uint32_t addr) {
    asm volatile("ldmatrix.sync.aligned.m8n8.x4.shared.b16 {%0,%1,%2,%3}, [%4];"
                 : "=r"(r0), "=r"(r1), "=r"(r2), "=r"(r3) : "r"(addr));
}
__device__ __forceinline__ void mma_f16(float* d, const uint32_t* a,
                                        uint32_t b0, uint32_t b1) {
    asm volatile(
        "mma.sync.aligned.m16n8k16.row.col.f32.f16.f16.f32 "
        "{%0,%1,%2,%3}, {%4,%5,%6,%7}, {%8,%9}, {%0,%1,%2,%3};"
        : "+f"(d[0]), "+f"(d[1]), "+f"(d[2]), "+f"(d[3])
        : "r"(a[0]), "r"(a[1]), "r"(a[2]), "r"(a[3]), "r"(b0), "r"(b1));
}
__device__ __forceinline__ void cp16(uint32_t dst, const void* src) {
    asm volatile("cp.async.cg.shared.global [%0], [%1], 16;"
                 :: "r"(dst), "l"(src));
}
#define CP_COMMIT() asm volatile("cp.async.commit_group;" ::: "memory")
#define CP_WAIT1()  asm volatile("cp.async.wait_group 1;" ::: "memory")

// ---------------------------------------------------------------------------
// Kernel P (fused front-end):
//   blocks [0, 8):        per-batch valid length from pad
//   blocks [8, 520):      tiled transpose + fp16 round of W1 (32x32 tiles)
//   blocks [520, 520+MM): per-token X fp32->fp16 convert; a token is valid
//                         iff pad[t]==0 (padding is trailing), so no
//                         dependency on g_len.
// ---------------------------------------------------------------------------
__global__ __launch_bounds__(256, 4)
void prep_kernel(const unsigned int* __restrict__ pad,
                 const float* __restrict__ W1,
                 const float* __restrict__ X)
{
    const int tid = threadIdx.x;
    if (blockIdx.x < BQ) {
        __shared__ int ired[256];
        const int b = blockIdx.x;
        if (b == 0 && tid == 0) g_nflag = 0;
        int lc = 0;
        for (int s = tid; s < SQ; s += 256)
            lc += (pad[b * SQ + s] == 0u) ? 1 : 0;
        ired[tid] = lc;
        __syncthreads();
        for (int o = 128; o > 0; o >>= 1) {
            if (tid < o) ired[tid] += ired[tid + o];
            __syncthreads();
        }
        if (tid == 0) g_len[b] = ired[0];
    } else if (blockIdx.x < BQ + 512) {
        __shared__ float tile[32][33];
        const int idx = blockIdx.x - BQ;          // 0..511
        const int k0 = (idx & 31) * 32;           // 32 k-tiles
        const int n0 = (idx >> 5) * 32;           // 16 n-tiles
        const int tx = tid & 31;
        const int ty = tid >> 5;

#pragma unroll
        for (int j = 0; j < 4; j++) {
            const int k = k0 + ty + j * 8;
            tile[ty + j * 8][tx] = W1[(size_t)k * DH + n0 + tx];
        }
        __syncthreads();

#pragma unroll
        for (int j = 0; j < 4; j++) {
            const int n = n0 + ty + j * 8;
            g_w1h[(size_t)n * DD + k0 + tx] =
                __float2half_rn(tile[tx][ty + j * 8]);
        }
    } else {
        const int t = blockIdx.x - (BQ + 512);
        if (pad[t] != 0u) return;          // trailing padding: never observable
        const int i = t * 256 + tid;       // per 4 elements
        const float4 v = ((const float4*)X)[i];
        __half2 h0 = __floats2half2_rn(v.x, v.y);
        __half2 h1 = __floats2half2_rn(v.z, v.w);
        uint2 o;
        o.x = *(uint32_t*)&h0;
        o.y = *(uint32_t*)&h1;
        ((uint2*)g_xh)[i] = o;
    }
}

// ---------------------------------------------------------------------------
// Kernel A: pure fp16 HMMA GEMM, TM=128 x TN=64 tile, 2-stage cp.async,
// 4 CTAs/SM (8 warps/SMSP). Padded M-tiles skipped.
// ---------------------------------------------------------------------------
__global__ __launch_bounds__(256, 4)
void gemm_hmma(const float* __restrict__ b1,
               const float* __restrict__ W2)
{
    extern __shared__ char smem[];
    const uint32_t sbase = smem_u32(smem);
    const int tid = threadIdx.x;
    const int wid = tid >> 5;
    const int lane = tid & 31;
    const int wm = wid & 3;          // M quadrant (32 rows)
    const int wn = wid >> 2;         // N half (32 cols)
    const int n0 = blockIdx.x * TN;
    const int m0 = blockIdx.y * TM;

    // Early exit: tile fully in trailing padding -> logits never read.
    const int bq = m0 >> 12;
    const int s0 = m0 & (SQ - 1);
    if (s0 >= g_len[bq]) return;

    float* b1s = (float*)(smem + SM_B1);
    float* w2s = (float*)(smem + SM_W2);
    float (*red)[2] = (float(*)[2])(smem + SM_RED);
    if (tid < TN) {
        b1s[tid] = b1[n0 + tid];
        w2s[tid] = W2[n0 + tid];
    }

    float acc[2][4][4];
#pragma unroll
    for (int mt = 0; mt < 2; mt++)
#pragma unroll
        for (int nt = 0; nt < 4; nt++)
#pragma unroll
            for (int e = 0; e < 4; e++) acc[mt][nt][e] = 0.0f;

    // A cp mapping: 2 threads per row (halves of 64-K)
    const int arow = tid >> 1;
    const int ahalf = tid & 1;
    const int arx = arow & 7;
    const uint32_t arb = (uint32_t)arow * 128u;
    // B cp mapping: 4 threads per row (quarters)
    const int brow = tid >> 2;
    const int bq4 = tid & 3;
    const int brx = brow & 7;
    const uint32_t brb = (uint32_t)brow * 128u;

    const __half* Ap = g_xh + (size_t)(m0 + arow) * DD + ahalf * 32;
    const __half* Bp = g_w1h + (size_t)(n0 + brow) * DD + bq4 * 16;

#define CP_CHUNK(c, st) do {                                                \
    const int _k0 = (c) * BK;                                               \
    const uint32_t _sa = sbase + SM_TILE + (st) * STAGE_SZ;                 \
    _Pragma("unroll")                                                       \
    for (int j = 0; j < 4; j++) {                                           \
        const uint32_t _co = (uint32_t)(((ahalf * 4 + j) ^ arx) * 16);      \
        cp16(_sa + arb + _co, Ap + _k0 + j * 8);                            \
    }                                                                       \
    _Pragma("unroll")                                                       \
    for (int j = 0; j < 2; j++) {                                           \
        const uint32_t _co = (uint32_t)(((bq4 * 2 + j) ^ brx) * 16);        \
        cp16(_sa + 16384 + brb + _co, Bp + _k0 + j * 8);                    \
    }                                                                       \
} while (0)

    // Prologue: fill both stages
    CP_CHUNK(0, 0);
    CP_COMMIT();
    CP_CHUNK(1, 1);
    CP_COMMIT();

    for (int c = 0; c < NCH; c++) {
        const int st = c & 1;
        CP_WAIT1();
        __syncthreads();

        const uint32_t abase = sbase + SM_TILE + st * STAGE_SZ;
#pragma unroll
        for (int ks = 0; ks < 4; ks++) {
            uint32_t a[2][4];        // [mtile][4]
            uint32_t bb[2][4];       // [npair][4]
            const int cc = ks * 2 + (lane >> 4);
#pragma unroll
            for (int mt = 0; mt < 2; mt++) {
                const int r = wm * 32 + mt * 16 + (lane & 15);
                const uint32_t addr = abase + r * 128 + ((cc ^ (r & 7)) * 16);
                ldm_x4(a[mt][0], a[mt][1], a[mt][2], a[mt][3], addr);
            }
#pragma unroll
            for (int np = 0; np < 2; np++) {
                const int r = wn * 32 + np * 16 + (lane & 15);
                const uint32_t addr = abase + 16384
                                    + r * 128 + ((cc ^ (r & 7)) * 16);
                ldm_x4(bb[np][0], bb[np][1], bb[np][2], bb[np][3], addr);
            }
#pragma unroll
            for (int mt = 0; mt < 2; mt++)
#pragma unroll
                for (int nt = 0; nt < 4; nt++) {
                    const int np = nt >> 1, sel = nt & 1;
                    mma_f16(acc[mt][nt], a[mt], bb[np][sel], bb[np][sel + 2]);
                }
        }
        __syncthreads();
        if (c + 2 < NCH) {
            CP_CHUNK(c + 2, st);
            CP_COMMIT();
        } else {
            CP_COMMIT();
        }
    }

    // Epilogue: p = sum_cols relu(acc + b1) * w2, reduce across quads + wn.
#pragma unroll
    for (int mt = 0; mt < 2; mt++) {
        float p0 = 0.0f, p1 = 0.0f;
#pragma unroll
        for (int nt = 0; nt < 4; nt++) {
            const int cl = wn * 32 + nt * 8 + (lane & 3) * 2;
            const float w0 = w2s[cl], w1v = w2s[cl + 1];
            const float c0 = b1s[cl], c1 = b1s[cl + 1];
            p0 = fmaf(fmaxf(acc[mt][nt][0] + c0, 0.0f), w0, p0);
            p0 = fmaf(fmaxf(acc[mt][nt][1] + c1, 0.0f), w1v, p0);
            p1 = fmaf(fmaxf(acc[mt][nt][2] + c0, 0.0f), w0, p1);
            p1 = fmaf(fmaxf(acc[mt][nt][3] + c1, 0.0f), w1v, p1);
        }
        p0 += __shfl_xor_sync(0xffffffffu, p0, 1);
        p0 += __shfl_xor_sync(0xffffffffu, p0, 2);
        p1 += __shfl_xor_sync(0xffffffffu, p1, 1);
        p1 += __shfl_xor_sync(0xffffffffu, p1, 2);
        if ((lane & 3) == 0) {
            const int r0 = wm * 32 + mt * 16 + (lane >> 2);
            red[r0][wn] = p0;
            red[r0 + 8][wn] = p1;
        }
    }
    __syncthreads();
    if (tid < TM)
        g_yp[blockIdx.x][m0 + tid] = red[tid][0] + red[tid][1];
}

// ---------------------------------------------------------------------------
// Kernel B1: sum partials -> z, flag tokens within BAND of threshold.
// ---------------------------------------------------------------------------
__global__ __launch_bounds__(256, 8)
void zflag_kernel(const float* __restrict__ b2)
{
    const int t = blockIdx.x * 256 + threadIdx.x;
    const int b = t >> 12;
    const int s = t & (SQ - 1);
    if (s >= g_len[b]) { g_z[t] = 0.0f; return; }
    float z = b2[0];
#pragma unroll
    for (int g = 0; g < NG; g++) z += g_yp[g][t];
    g_z[t] = z;
    if (fabsf(z - ZTHR) < BAND) {
        int i = atomicAdd(&g_nflag, 1);
        if (i < MAXFLAG) g_flag[i] = t;
    }
}

// ---------------------------------------------------------------------------
// Kernel R: exact fp32 recompute of flagged tokens' logits.
// One block (1024 thr) per flagged token: 8 k-groups x 128 h-quads.
// ---------------------------------------------------------------------------
__global__ __launch_bounds__(1024, 1)
void refine_kernel(const float* __restrict__ X,
                   const float* __restrict__ W1,
                   const float* __restrict__ b1,
                   const float* __restrict__ W2,
                   const float* __restrict__ b2)
{
    __shared__ float  xs[DD];           // 4KB
    __shared__ float4 part[8][128];     // 16KB
    __shared__ float  rr[4];
    const int tid = threadIdx.x;
    const int kg = tid >> 7;            // 0..7
    const int hq = tid & 127;           // h quad: h = hq*4..hq*4+3
    int n = g_nflag;
    if (n > MAXFLAG) n = MAXFLAG;

    for (int i = blockIdx.x; i < n; i += gridDim.x) {
        const int t = g_flag[i];
        if (tid < DD) xs[tid] = X[(size_t)t * DD + tid];
        __syncthreads();

        const float4* Wp = (const float4*)W1 + hq;
        float4 acc = make_float4(0.0f, 0.0f, 0.0f, 0.0f);
        const int k0 = kg * 128;
#pragma unroll 8
        for (int k = k0; k < k0 + 128; k++) {
            const float xk = xs[k];
            const float4 w = Wp[(size_t)k * (DH / 4)];
            acc.x = fmaf(xk, w.x, acc.x);
            acc.y = fmaf(xk, w.y, acc.y);
            acc.z = fmaf(xk, w.z, acc.z);
            acc.w = fmaf(xk, w.w, acc.w);
        }
        part[kg][hq] = acc;
        __syncthreads();

        if (tid < 128) {
            float4 s = part[0][tid];
#pragma unroll
            for (int g = 1; g < 8; g++) {
                const float4 q = part[g][tid];
                s.x += q.x; s.y += q.y; s.z += q.z; s.w += q.w;
            }
            const float4 bb = ((const float4*)b1)[tid];
            const float4 ww = ((const float4*)W2)[tid];
            float p;
            p  = fmaxf(s.x + bb.x, 0.0f) * ww.x;
            p += fmaxf(s.y + bb.y, 0.0f) * ww.y;
            p += fmaxf(s.z + bb.z, 0.0f) * ww.z;
            p += fmaxf(s.w + bb.w, 0.0f) * ww.w;
            p += __shfl_xor_sync(0xffffffffu, p, 16);
            p += __shfl_xor_sync(0xffffffffu, p, 8);
            p += __shfl_xor_sync(0xffffffffu, p, 4);
            p += __shfl_xor_sync(0xffffffffu, p, 2);
            p += __shfl_xor_sync(0xffffffffu, p, 1);
            if ((tid & 31) == 0) rr[tid >> 5] = p;
        }
        __syncthreads();
        if (tid == 0) g_z[t] = rr[0] + rr[1] + rr[2] + rr[3] + b2[0];
        __syncthreads();
    }
}

// ---------------------------------------------------------------------------
// Kernel B2: per-batch squash, max/adjust, compaction. 1024 threads.
// ---------------------------------------------------------------------------
__global__ __launch_bounds__(1024, 1)
void gate_select_kernel(float* __restrict__ vpad_out, int write_vpad)
{
    const int b = blockIdx.x;
    const int tid = threadIdx.x;

    __shared__ float ysm[SQ];
    __shared__ float fred[1024];
    __shared__ int   cnt[1024];

    const int length = g_len[b];

    float mx = 0.0f;
    for (int s = tid; s < SQ; s += 1024) {
        float y = (s < length)
                ? (1.0f + tanhf(10.0f * g_z[b * SQ + s])) * 0.5f : 0.0f;
        ysm[s] = y;
        mx = fmaxf(mx, y);
    }
    fred[tid] = mx;
    __syncthreads();
    for (int o = 512; o > 0; o >>= 1) {
        if (tid < o) fred[tid] = fmaxf(fred[tid], fred[tid + o]);
        __syncthreads();
    }
    const float adjust = fmaxf(0.0f, EPSV + THRESHOLD - fred[0]);
    __syncthreads();

    for (int s = tid; s < SQ; s += 1024) {
        float yf = ysm[s] + adjust;
        ysm[s] = yf;
        g_yfin[b * SQ + s] = yf;
    }
    __syncthreads();

    const int CH = SQ / 1024;     // 4 contiguous positions per thread
    const int base = tid * CH;
    int c = 0;
#pragma unroll
    for (int i = 0; i < CH; i++) {
        int s = base + i;
        c += (ysm[s] > THRESHOLD && s < length) ? 1 : 0;
    }
    cnt[tid] = c;
    __syncthreads();
    for (int o = 1; o < 1024; o <<= 1) {
        int v = (tid >= o) ? cnt[tid - o] : 0;
        __syncthreads();
        cnt[tid] += v;
        __syncthreads();
    }
    int off = cnt[tid] - c;
#pragma unroll
    for (int i = 0; i < CH; i++) {
        int s = base + i;
        if (ysm[s] > THRESHOLD && s < length) g_idx[b][off++] = s;
    }
    const int nl = cnt[1023];
    if (tid == 0) g_newlen[b] = nl;

    if (write_vpad) {
        for (int s = tid; s < SQ; s += 1024)
            vpad_out[b * SQ + s] = (s >= nl) ? 1.0f : 0.0f;
    }
}

// ---------------------------------------------------------------------------
// Kernel C: scatter compacted rows, 4 rows per block (MLP 4).
// ---------------------------------------------------------------------------
__global__ __launch_bounds__(256, 4)
void scatter_kernel(const float* __restrict__ X, float* __restrict__ V)
{
    const int b = blockIdx.y;
    const int r0 = blockIdx.x * 4;
    const int tid = threadIdx.x;
    const int nl = g_newlen[b];

#pragma unroll
    for (int j = 0; j < 4; j++) {
        const int r = r0 + j;
        float4* vrow = (float4*)(V + ((size_t)b * SQ + r) * DD);
        if (r < nl) {
            const int s = g_idx[b][r];
            const float g = g_yfin[b * SQ + s];
            const float4* xrow = (const float4*)(X + ((size_t)b * SQ + s) * DD);
            float4 xv = xrow[tid];
            vrow[tid] = make_float4(xv.x * g, xv.y * g, xv.z * g, xv.w * g);
        } else {
            vrow[tid] = make_float4(0.0f, 0.0f, 0.0f, 0.0f);
        }
    }
}

// ---------------------------------------------------------------------------
extern "C" void kernel_launch(void* const* d_in, const int* in_sizes, int n_in,
                              void* d_out, int out_size)
{
    const float*        x   = (const float*)d_in[0];
    const unsigned int* pad = (const unsigned int*)d_in[1];
    const float*        W1  = (const float*)d_in[2];
    const float*        b1  = (const float*)d_in[3];
    const float*        W2  = (const float*)d_in[4];
    const float*        b2  = (const float*)d_in[5];
    float* out = (float*)d_out;

    const long v_elems = (long)MM * DD;
    int write_vpad = (out_size > v_elems) ? 1 : 0;
    float* vpad = out + v_elems;

    cudaFuncSetAttribute(gemm_hmma,
                         cudaFuncAttributeMaxDynamicSharedMemorySize, SM_TOT);

    prep_kernel<<<BQ + 512 + MM, 256>>>(pad, W1, x);
    gemm_hmma<<<dim3(NG, MM / TM), 256, SM_TOT>>>(b1, W2);
    zflag_kernel<<<MM / 256, 256>>>(b2);
    refine_kernel<<<128, 1024>>>(x, W1, b1, W2, b2);
    gate_select_kernel<<<BQ, 1024>>>(vpad, write_vpad);
    scatter_kernel<<<dim3(SQ / 4, BQ), 256>>>(x, out);
}